// round 15
// baseline (speedup 1.0000x reference)
#include <cuda_runtime.h>
#include <cuda_fp16.h>
#include <cstdint>
#include <math.h>

// SwinTransformerBlockV2 fused kernel, v12.
// Shift (8,8) multiple of window (4,4) => shift cancels, mask == 0.
// Tensor-core everything, FP16 fragments.
// v12: fragment-interleaved activation layouts -> all GEMM A-fragment groups
// are single LDS.64s (conflict-free strides 40/136); MLP merged to 2 barriers
// (H spans dead Q+K f32 regions); fc2 single KS=16 pass with deep B prefetch.
// Precision: qkv + attention S = 3-MMA hi/lo; P/V/O single fp16; proj/fc1/fc2
// B single fp16.

#define NTHREADS 256
#define LD   68      // f32 row stride (x, q, k, partials, h2)
#define LDX  40      // u32 row stride for XH/XL fragment-interleaved
#define LDH  136     // u32 row stride for H fragment-interleaved

#define OFF_X    0          // f32 [64][68] x -> x1 in place
#define OFF_Q    4352       // f32 q; then bufA; then H (spans Q+K, 64*136 u32)
#define OFF_K    8704       // f32 k; then bufB; then H upper part
#define OFF_V    13056      // half Vt[ch][token] stride 136h; then h2 (f32)
#define OFF_XH   17408      // u32 [64][40] x hi -> x1 packed fp16
#define OFF_XL   19968      // u32 [64][40] x lo (dead after qkv)
#define SMEM_FLOATS 22528
#define SMEM_BYTES  (SMEM_FLOATS * 4)

__device__ float g_tab[49 * 4];
__device__ float g_biasf[4 * 256];   // fragment layout: [hh][lane][8]
__device__ float g_scale[4];

__device__ uint4 g_fqkv[3072];
__device__ uint2 g_fproj[1024];
__device__ uint2 g_ffc1[4096];
__device__ uint2 g_ffc2[4096];

// ---------------------------------------------------------------------------
__device__ __forceinline__ uint32_t packh1(float x, float y) {
    __half2 h = __floats2half2_rn(x, y);
    return *reinterpret_cast<uint32_t*>(&h);
}

__device__ __forceinline__ uint32_t splith(float x, float y, uint32_t& lo) {
    __half2 h = __floats2half2_rn(x, y);
    float2 f = __half22float2(h);
    __half2 l = __floats2half2_rn(x - f.x, y - f.y);
    lo = *reinterpret_cast<uint32_t*>(&l);
    return *reinterpret_cast<uint32_t*>(&h);
}

__device__ __forceinline__ float gelu1(float v) {
    return v * 0.5f * (1.0f + erff(v * 0.70710678118654752f));
}

// ---------------------------------------------------------------------------
// Setup kernels
// ---------------------------------------------------------------------------
__device__ __forceinline__ float cpb_coord(int d) {
    float t = (8.0f / 3.0f) * (float)d;
    float v = log2f(fabsf(t) + 1.0f) / 3.0f;
    return (t < 0.0f) ? -v : v;
}

__global__ void cpb_kernel(const float* __restrict__ w1, const float* __restrict__ b1,
                           const float* __restrict__ w2) {
    int q = blockIdx.x >> 2;
    int h = blockIdx.x & 3;
    int a = q / 7;
    int b = q % 7;
    float c0 = cpb_coord(a - 3);
    float c1 = cpb_coord(b - 3);
    int tid = threadIdx.x;
    float s = 0.0f;
#pragma unroll
    for (int r = 0; r < 4; r++) {
        int j = tid + r * 128;
        float u = c0 * w1[2 * j] + c1 * w1[2 * j + 1] + b1[j];
        u = fmaxf(u, 0.0f);
        s += u * w2[h * 512 + j];
    }
    __shared__ float red[4];
#pragma unroll
    for (int o = 16; o > 0; o >>= 1) s += __shfl_xor_sync(0xffffffffu, s, o);
    if ((tid & 31) == 0) red[tid >> 5] = s;
    __syncthreads();
    if (tid == 0) g_tab[q * 4 + h] = red[0] + red[1] + red[2] + red[3];
}

__global__ void expand_kernel(const float* __restrict__ ls) {
    int e = blockIdx.x * 256 + threadIdx.x;
    int hh = e >> 8;
    int lane = (e >> 3) & 31;
    int i = e & 7;
    int g = lane >> 2;
    int t = lane & 3;
    int r = g + ((i & 2) ? 8 : 0);
    int c = 2 * t + (i & 1) + ((i & 4) ? 8 : 0);
    int idx = ((r >> 2) - (c >> 2) + 3) * 7 + ((r & 3) - (c & 3) + 3);
    float v = g_tab[idx * 4 + hh];
    g_biasf[hh * 256 + lane * 8 + i] = 16.0f / (1.0f + expf(-v));
    if (e < 4) g_scale[e] = expf(fminf(ls[e], logf(100.0f)));
}

__global__ void wsplit_kernel(const float* __restrict__ qkv_w, const float* __restrict__ proj_w,
                              const float* __restrict__ fc1_w, const float* __restrict__ fc2_w) {
    int i = blockIdx.x * 256 + threadIdx.x;
    if (i >= 12288) return;
    const float* src;
    int q, K, lgKS, mode;
    uint4* dst4 = 0;
    uint2* dst2 = 0;
    if (i < 3072) {
        q = i; src = qkv_w; dst4 = g_fqkv; K = 64; lgKS = 2; mode = 0;
    } else if (i < 4096) {
        q = i - 3072; src = proj_w; dst2 = g_fproj; K = 64; lgKS = 2; mode = 1;
    } else if (i < 8192) {
        q = i - 4096; src = fc1_w; dst2 = g_ffc1; K = 64; lgKS = 2; mode = 1;
    } else {
        q = i - 8192; src = fc2_w; dst2 = g_ffc2; K = 256; lgKS = 4; mode = 1;
    }
    int t  = q & 3;
    int g  = (q >> 2) & 7;
    int ks = (q >> 5) & ((1 << lgKS) - 1);
    int o  = q >> (5 + lgKS);
    int n  = o * 8 + g;
    int p0 = ks * 8 + t;
    int p1 = p0 + 4;
    const float* row = src + n * K;
    if (mode == 0) {
        uint32_t lo0, lo1;
        uint32_t hi0 = splith(row[2 * p0], row[2 * p0 + 1], lo0);
        uint32_t hi1 = splith(row[2 * p1], row[2 * p1 + 1], lo1);
        dst4[q] = make_uint4(hi0, hi1, lo0, lo1);
    } else {
        uint32_t hi0 = packh1(row[2 * p0], row[2 * p0 + 1]);
        uint32_t hi1 = packh1(row[2 * p1], row[2 * p1 + 1]);
        dst2[q] = make_uint2(hi0, hi1);
    }
}

// ---------------------------------------------------------------------------
__device__ __forceinline__ void mma_f16(float* dd,
        uint32_t a0, uint32_t a1, uint32_t a2, uint32_t a3,
        uint32_t b0, uint32_t b1) {
    asm volatile("mma.sync.aligned.m16n8k16.row.col.f32.f16.f16.f32 "
                 "{%0,%1,%2,%3}, {%4,%5,%6,%7}, {%8,%9}, {%0,%1,%2,%3};\n"
                 : "+f"(dd[0]), "+f"(dd[1]), "+f"(dd[2]), "+f"(dd[3])
                 : "r"(a0), "r"(a1), "r"(a2), "r"(a3), "r"(b0), "r"(b1));
}

// qkv (M2, 3-term): A = fragment-interleaved hi/lo (uint2 stride 20), B uint4
template<int NT, int KSTEPS>
__device__ __forceinline__ void gemm2_A3f(const uint2* Xh, const uint2* Xl,
        int mrow, const uint4* __restrict__ Bf, int KS_total, int o0,
        float (&d)[2][NT][4], int g, int t) {
    uint4 bn[NT];
#pragma unroll
    for (int j = 0; j < NT; j++)
        bn[j] = Bf[(o0 + j) * (KS_total * 32) + g * 4 + t];
#pragma unroll
    for (int ks = 0; ks < KSTEPS; ks++) {
        uint4 bc[NT];
#pragma unroll
        for (int j = 0; j < NT; j++) bc[j] = bn[j];
        if (ks + 1 < KSTEPS) {
#pragma unroll
            for (int j = 0; j < NT; j++)
                bn[j] = Bf[(o0 + j) * (KS_total * 32) + (ks + 1) * 32 + g * 4 + t];
        }
        uint32_t ah[2][4], al[2][4];
#pragma unroll
        for (int i2 = 0; i2 < 2; i2++) {
            int rb = (mrow + i2 * 16 + g) * 20 + ks * 4 + t;
            uint2 hg = Xh[rb];
            uint2 h8 = Xh[rb + 160];
            uint2 lg = Xl[rb];
            uint2 l8 = Xl[rb + 160];
            ah[i2][0] = hg.x; ah[i2][1] = h8.x; ah[i2][2] = hg.y; ah[i2][3] = h8.y;
            al[i2][0] = lg.x; al[i2][1] = l8.x; al[i2][2] = lg.y; al[i2][3] = l8.y;
        }
#pragma unroll
        for (int j = 0; j < NT; j++) {
#pragma unroll
            for (int i2 = 0; i2 < 2; i2++) {
                mma_f16(d[i2][j], ah[i2][0], ah[i2][1], ah[i2][2], ah[i2][3], bc[j].x, bc[j].y);
                mma_f16(d[i2][j], al[i2][0], al[i2][1], al[i2][2], al[i2][3], bc[j].x, bc[j].y);
                mma_f16(d[i2][j], ah[i2][0], ah[i2][1], ah[i2][2], ah[i2][3], bc[j].z, bc[j].w);
            }
        }
    }
}

// fc1 (M2, single-term): A = fragment-interleaved fp16 (uint2 stride 20)
template<int NT, int KSTEPS>
__device__ __forceinline__ void gemm2_A1f(const uint2* Xh,
        int mrow, const uint2* __restrict__ Bf, int KS_total, int o0,
        float (&d)[2][NT][4], int g, int t) {
    uint2 bn[NT];
#pragma unroll
    for (int j = 0; j < NT; j++)
        bn[j] = Bf[(o0 + j) * (KS_total * 32) + g * 4 + t];
#pragma unroll
    for (int ks = 0; ks < KSTEPS; ks++) {
        uint2 bc[NT];
#pragma unroll
        for (int j = 0; j < NT; j++) bc[j] = bn[j];
        if (ks + 1 < KSTEPS) {
#pragma unroll
            for (int j = 0; j < NT; j++)
                bn[j] = Bf[(o0 + j) * (KS_total * 32) + (ks + 1) * 32 + g * 4 + t];
        }
        uint32_t ah[2][4];
#pragma unroll
        for (int i2 = 0; i2 < 2; i2++) {
            int rb = (mrow + i2 * 16 + g) * 20 + ks * 4 + t;
            uint2 hg = Xh[rb];
            uint2 h8 = Xh[rb + 160];
            ah[i2][0] = hg.x; ah[i2][1] = h8.x; ah[i2][2] = hg.y; ah[i2][3] = h8.y;
        }
#pragma unroll
        for (int j = 0; j < NT; j++) {
#pragma unroll
            for (int i2 = 0; i2 < 2; i2++) {
                mma_f16(d[i2][j], ah[i2][0], ah[i2][1], ah[i2][2], ah[i2][3], bc[j].x, bc[j].y);
            }
        }
    }
}

// fc2 (M1, single-term, KS=16): A = H fragment-interleaved (uint2 stride 68)
template<int NT, int KSTEPS>
__device__ __forceinline__ void gemm1_A1f(const uint2* Hh,
        int mrow, const uint2* __restrict__ Bf, int KS_total, int o0,
        float (&d)[NT][4], int g, int t) {
    uint2 bn[NT];
#pragma unroll
    for (int j = 0; j < NT; j++)
        bn[j] = Bf[(o0 + j) * (KS_total * 32) + g * 4 + t];
#pragma unroll
    for (int ks = 0; ks < KSTEPS; ks++) {
        uint2 bc[NT];
#pragma unroll
        for (int j = 0; j < NT; j++) bc[j] = bn[j];
        if (ks + 1 < KSTEPS) {
#pragma unroll
            for (int j = 0; j < NT; j++)
                bn[j] = Bf[(o0 + j) * (KS_total * 32) + (ks + 1) * 32 + g * 4 + t];
        }
        int rb = (mrow + g) * 68 + ks * 4 + t;
        uint2 ug = Hh[rb];
        uint2 u8 = Hh[rb + 8 * 68];
#pragma unroll
        for (int j = 0; j < NT; j++) {
            mma_f16(d[j], ug.x, u8.x, ug.y, u8.y, bc[j].x, bc[j].y);
        }
    }
}

__device__ __forceinline__ int token_gaddr(int blk, int lt) {
    int wi = blk * 4 + (lt >> 4);
    int n  = lt & 15;
    int b  = wi >> 12;
    int r  = wi & 4095;
    int wh = r >> 6;
    int ww = r & 63;
    int row = wh * 4 + (n >> 2);
    int col = ww * 4 + (n & 3);
    return ((b * 256 + row) * 256 + col) * 64;
}

// ---------------------------------------------------------------------------
__global__ __launch_bounds__(NTHREADS, 2)
void swin_kernel(const float* __restrict__ x,
                 const float* __restrict__ qkv_b, const float* __restrict__ proj_b,
                 const float* __restrict__ n1g, const float* __restrict__ n1b,
                 const float* __restrict__ n2g, const float* __restrict__ n2b,
                 const float* __restrict__ fc1_b, const float* __restrict__ fc2_b,
                 float* __restrict__ out) {
    extern __shared__ float sm[];
    uint32_t* smu = (uint32_t*)sm;
    __shared__ float s_qkvb[192];
    __shared__ float s_projb[64];
    __shared__ float s_fc1b[256];
    __shared__ float s_fc2b[64];
    __shared__ float s_n1g[64];
    __shared__ float s_n1b[64];
    __shared__ float s_n2g[64];
    __shared__ float s_n2b[64];
    __shared__ float s_scale[4];

    const int tid  = threadIdx.x;
    const int warp = tid >> 5;
    const int lane = tid & 31;
    const int g = lane >> 2;
    const int t = lane & 3;
    const int mt2 = warp >> 2;
    const int nh4 = warp & 3;
    const int mrow2 = mt2 * 32;
    const int mt1 = warp & 3;
    const int nh1 = warp >> 2;
    const int mrow1 = mt1 * 16;

    // ---- phase 0: params + x tile (f32 + fragment-interleaved split) ----
    if (tid < 192) s_qkvb[tid] = (tid >= 64 && tid < 128) ? 0.0f : qkv_b[tid];
    if (tid < 64) {
        s_projb[tid] = proj_b[tid];
        s_fc2b[tid]  = fc2_b[tid];
        s_n1g[tid] = n1g[tid];
        s_n1b[tid] = n1b[tid];
        s_n2g[tid] = n2g[tid];
        s_n2b[tid] = n2b[tid];
    }
    s_fc1b[tid] = fc1_b[tid];
    if (tid >= 192 && tid < 196) s_scale[tid - 192] = g_scale[tid - 192];

    {
        int lt = tid >> 2;
        int pp = tid & 3;
        int gbase = token_gaddr(blockIdx.x, lt);
        const float4* xp = (const float4*)(x + gbase + pp * 16);
        float4* xd = (float4*)(sm + OFF_X + lt * LD + pp * 16);
        uint32_t* xh = smu + OFF_XH + lt * LDX;
        uint32_t* xl = smu + OFF_XL + lt * LDX;
#pragma unroll
        for (int i = 0; i < 4; i++) {
            float4 v4 = xp[i];
            xd[i] = v4;
            uint32_t lo0, lo1;
            uint32_t hi0 = splith(v4.x, v4.y, lo0);
            uint32_t hi1 = splith(v4.z, v4.w, lo1);
            int q0 = 2 * i;
            int q1 = 2 * i + 1;
            int c0 = pp * 8 + 2 * (q0 & 3) + (q0 >> 2);
            int c1 = pp * 8 + 2 * (q1 & 3) + (q1 >> 2);
            xh[c0] = hi0;
            xh[c1] = hi1;
            xl[c0] = lo0;
            xl[c1] = lo1;
        }
    }
    __syncthreads();

    // ---- phase 1: QKV GEMM (M2, 3-term, NT=6); V -> half Vt ----
    __half* vt = (__half*)(sm + OFF_V);
    {
        float d[2][6][4];
#pragma unroll
        for (int i2 = 0; i2 < 2; i2++)
#pragma unroll
            for (int j = 0; j < 6; j++)
#pragma unroll
                for (int i = 0; i < 4; i++) d[i2][j][i] = 0.0f;
        gemm2_A3f<6, 4>((const uint2*)(smu + OFF_XH), (const uint2*)(smu + OFF_XL),
                        mrow2, g_fqkv, 4, nh4 * 6, d, g, t);
#pragma unroll
        for (int j = 0; j < 6; j++) {
            int c = nh4 * 48 + 8 * j + 2 * t;
            float b0 = s_qkvb[c];
            float b1 = s_qkvb[c + 1];
            if (c < 128) {
                int col = c & 63;
                float* dst = sm + (c < 64 ? OFF_Q : OFF_K);
#pragma unroll
                for (int i2 = 0; i2 < 2; i2++) {
                    int r = mrow2 + i2 * 16 + g;
                    *(float2*)(dst + r * LD + col)       = make_float2(d[i2][j][0] + b0, d[i2][j][1] + b1);
                    *(float2*)(dst + (r + 8) * LD + col) = make_float2(d[i2][j][2] + b0, d[i2][j][3] + b1);
                }
            } else {
                int col = c - 128;
#pragma unroll
                for (int i2 = 0; i2 < 2; i2++) {
                    int r = mrow2 + i2 * 16 + g;
                    vt[col * 136 + r]           = __float2half_rn(d[i2][j][0] + b0);
                    vt[(col + 1) * 136 + r]     = __float2half_rn(d[i2][j][1] + b1);
                    vt[col * 136 + r + 8]       = __float2half_rn(d[i2][j][2] + b0);
                    vt[(col + 1) * 136 + r + 8] = __float2half_rn(d[i2][j][3] + b1);
                }
            }
        }
    }
    __syncthreads();

    // ---- phase 2: attention (S 3-term; P,V,O single fp16) + chained proj ----
    {
        float cacc[8][4];
        bool wbias = ((warp & 1) == 0);
#pragma unroll
        for (int j = 0; j < 8; j++) {
            float b0 = wbias ? s_projb[8 * j + 2 * t] : 0.0f;
            float b1 = wbias ? s_projb[8 * j + 2 * t + 1] : 0.0f;
            cacc[j][0] = b0;
            cacc[j][1] = b1;
            cacc[j][2] = b0;
            cacc[j][3] = b1;
        }
        int wl = warp >> 1;
        int r0 = wl * 16;
        const uint32_t* vtu = (const uint32_t*)(sm + OFF_V);

#pragma unroll 1
        for (int it = 0; it < 2; it++) {
            int hh = (warp & 1) * 2 + it;

            const float* Qb = sm + OFF_Q + (r0 + g) * LD + hh * 16;
            float2 q0 = *(const float2*)(Qb + 2 * t);
            float2 q1 = *(const float2*)(Qb + 2 * t + 8);
            float2 q2 = *(const float2*)(Qb + 8 * LD + 2 * t);
            float2 q3 = *(const float2*)(Qb + 8 * LD + 2 * t + 8);
            float ssA = q0.x * q0.x + q0.y * q0.y + q1.x * q1.x + q1.y * q1.y;
            float ssB = q2.x * q2.x + q2.y * q2.y + q3.x * q3.x + q3.y * q3.y;
            ssA += __shfl_xor_sync(0xffffffffu, ssA, 1);
            ssA += __shfl_xor_sync(0xffffffffu, ssA, 2);
            ssB += __shfl_xor_sync(0xffffffffu, ssB, 1);
            ssB += __shfl_xor_sync(0xffffffffu, ssB, 2);
            float scl = s_scale[hh];
            float iA = scl * rsqrtf(fmaxf(ssA, 1e-24f));
            float iB = scl * rsqrtf(fmaxf(ssB, 1e-24f));
            q0.x *= iA; q0.y *= iA; q1.x *= iA; q1.y *= iA;
            q2.x *= iB; q2.y *= iB; q3.x *= iB; q3.y *= iB;

            const float* Kb = sm + OFF_K + (r0 + g) * LD + hh * 16;
            float2 k0 = *(const float2*)(Kb + 2 * t);
            float2 k1 = *(const float2*)(Kb + 2 * t + 8);
            float2 k2 = *(const float2*)(Kb + 8 * LD + 2 * t);
            float2 k3 = *(const float2*)(Kb + 8 * LD + 2 * t + 8);
            float skA = k0.x * k0.x + k0.y * k0.y + k1.x * k1.x + k1.y * k1.y;
            float skB = k2.x * k2.x + k2.y * k2.y + k3.x * k3.x + k3.y * k3.y;
            skA += __shfl_xor_sync(0xffffffffu, skA, 1);
            skA += __shfl_xor_sync(0xffffffffu, skA, 2);
            skB += __shfl_xor_sync(0xffffffffu, skB, 1);
            skB += __shfl_xor_sync(0xffffffffu, skB, 2);
            float jA = rsqrtf(fmaxf(skA, 1e-24f));
            float jB = rsqrtf(fmaxf(skB, 1e-24f));
            k0.x *= jA; k0.y *= jA; k1.x *= jA; k1.y *= jA;
            k2.x *= jB; k2.y *= jB; k3.x *= jB; k3.y *= jB;

            uint32_t ql0, ql1, ql2, ql3, kl0, kl1, kl2, kl3;
            uint32_t qh0 = splith(q0.x, q0.y, ql0);
            uint32_t qh1 = splith(q1.x, q1.y, ql1);
            uint32_t qh2 = splith(q2.x, q2.y, ql2);
            uint32_t qh3 = splith(q3.x, q3.y, ql3);
            uint32_t kh0 = splith(k0.x, k0.y, kl0);
            uint32_t kh1 = splith(k1.x, k1.y, kl1);
            uint32_t kh2 = splith(k2.x, k2.y, kl2);
            uint32_t kh3 = splith(k3.x, k3.y, kl3);

            const float4* bf = (const float4*)(g_biasf + hh * 256 + lane * 8);
            float4 bb0 = bf[0];
            float4 bb1 = bf[1];
            float s0[4] = {bb0.x, bb0.y, bb0.z, bb0.w};
            float s1[4] = {bb1.x, bb1.y, bb1.z, bb1.w};
            mma_f16(s0, qh0, qh2, qh1, qh3, kh0, kh1);
            mma_f16(s0, ql0, ql2, ql1, ql3, kh0, kh1);
            mma_f16(s0, qh0, qh2, qh1, qh3, kl0, kl1);
            mma_f16(s1, qh0, qh2, qh1, qh3, kh2, kh3);
            mma_f16(s1, ql0, ql2, ql1, ql3, kh2, kh3);
            mma_f16(s1, qh0, qh2, qh1, qh3, kl2, kl3);

            float mA = fmaxf(fmaxf(s0[0], s0[1]), fmaxf(s1[0], s1[1]));
            float mB = fmaxf(fmaxf(s0[2], s0[3]), fmaxf(s1[2], s1[3]));
            mA = fmaxf(mA, __shfl_xor_sync(0xffffffffu, mA, 1));
            mA = fmaxf(mA, __shfl_xor_sync(0xffffffffu, mA, 2));
            mB = fmaxf(mB, __shfl_xor_sync(0xffffffffu, mB, 1));
            mB = fmaxf(mB, __shfl_xor_sync(0xffffffffu, mB, 2));
            s0[0] = __expf(s0[0] - mA);
            s0[1] = __expf(s0[1] - mA);
            s1[0] = __expf(s1[0] - mA);
            s1[1] = __expf(s1[1] - mA);
            s0[2] = __expf(s0[2] - mB);
            s0[3] = __expf(s0[3] - mB);
            s1[2] = __expf(s1[2] - mB);
            s1[3] = __expf(s1[3] - mB);
            float suA = s0[0] + s0[1] + s1[0] + s1[1];
            float suB = s0[2] + s0[3] + s1[2] + s1[3];
            suA += __shfl_xor_sync(0xffffffffu, suA, 1);
            suA += __shfl_xor_sync(0xffffffffu, suA, 2);
            suB += __shfl_xor_sync(0xffffffffu, suB, 1);
            suB += __shfl_xor_sync(0xffffffffu, suB, 2);
            float ivA = 1.0f / suA;
            float ivB = 1.0f / suB;

            uint32_t ph0 = packh1(s0[0], s0[1]);
            uint32_t ph1 = packh1(s0[2], s0[3]);
            uint32_t ph2 = packh1(s1[0], s1[1]);
            uint32_t ph3 = packh1(s1[2], s1[3]);

            int ch = hh * 16 + g;
            int vbase = ch * 68 + (r0 >> 1) + t;
            uint32_t vh0 = vtu[vbase];
            uint32_t vh1 = vtu[vbase + 4];
            uint32_t vh2 = vtu[vbase + 8 * 68];
            uint32_t vh3 = vtu[vbase + 8 * 68 + 4];

            float o0[4] = {0.0f, 0.0f, 0.0f, 0.0f};
            float o1[4] = {0.0f, 0.0f, 0.0f, 0.0f};
            mma_f16(o0, ph0, ph1, ph2, ph3, vh0, vh1);
            mma_f16(o1, ph0, ph1, ph2, ph3, vh2, vh3);

            o0[0] *= ivA; o0[1] *= ivA; o1[0] *= ivA; o1[1] *= ivA;
            o0[2] *= ivB; o0[3] *= ivB; o1[2] *= ivB; o1[3] *= ivB;

            uint32_t ahx0 = packh1(o0[0], o0[1]);
            uint32_t ahx1 = packh1(o0[2], o0[3]);
            uint32_t ahx2 = packh1(o1[0], o1[1]);
            uint32_t ahx3 = packh1(o1[2], o1[3]);
#pragma unroll
            for (int j = 0; j < 8; j++) {
                uint2 b = g_fproj[j * 128 + hh * 32 + g * 4 + t];
                mma_f16(cacc[j], ahx0, ahx1, ahx2, ahx3, b.x, b.y);
            }
        }
        __syncthreads();
        float* buf = sm + ((warp & 1) ? OFF_K : OFF_Q);
#pragma unroll
        for (int j = 0; j < 8; j++) {
            int c = 8 * j + 2 * t;
            *(float2*)(buf + (r0 + g) * LD + c)     = make_float2(cacc[j][0], cacc[j][1]);
            *(float2*)(buf + (r0 + g + 8) * LD + c) = make_float2(cacc[j][2], cacc[j][3]);
        }
    }
    __syncthreads();

    // ---- phase 3: LN1 + residual in place + pack x1 fp16 (frag layout) ----
    {
        int row = tid >> 2;
        int sub = tid & 3;
        const float* pa = sm + OFF_Q + row * LD + sub * 16;
        const float* pb = sm + OFF_K + row * LD + sub * 16;
        float av[16];
        float s = 0.0f;
#pragma unroll
        for (int c = 0; c < 16; c++) {
            av[c] = pa[c] + pb[c];
            s += av[c];
        }
        s += __shfl_xor_sync(0xffffffffu, s, 1);
        s += __shfl_xor_sync(0xffffffffu, s, 2);
        float mean = s * (1.0f / 64.0f);
        float vv = 0.0f;
#pragma unroll
        for (int c = 0; c < 16; c++) {
            float d2 = av[c] - mean;
            vv += d2 * d2;
        }
        vv += __shfl_xor_sync(0xffffffffu, vv, 1);
        vv += __shfl_xor_sync(0xffffffffu, vv, 2);
        float rstd = rsqrtf(vv * (1.0f / 64.0f) + 1e-5f);
        float* xr = sm + OFF_X + row * LD + sub * 16;
        const float* gg = s_n1g + sub * 16;
        const float* bbv = s_n1b + sub * 16;
        uint32_t* xh = smu + OFF_XH + row * LDX;
#pragma unroll
        for (int c2 = 0; c2 < 8; c2++) {
            float u0 = xr[2 * c2]     + (av[2 * c2]     - mean) * rstd * gg[2 * c2]     + bbv[2 * c2];
            float u1 = xr[2 * c2 + 1] + (av[2 * c2 + 1] - mean) * rstd * gg[2 * c2 + 1] + bbv[2 * c2 + 1];
            xr[2 * c2] = u0;
            xr[2 * c2 + 1] = u1;
            int col = sub * 8 + 2 * (c2 & 3) + (c2 >> 2);
            xh[col] = packh1(u0, u1);
        }
    }
    __syncthreads();

    // ---- phase 4: MLP — fc1 both halves (no mid barrier) then fc2 KS=16 ----
#pragma unroll 1
    for (int kh = 0; kh < 2; kh++) {
        float d[2][4][4];
#pragma unroll
        for (int i2 = 0; i2 < 2; i2++)
#pragma unroll
            for (int j = 0; j < 4; j++)
#pragma unroll
                for (int i = 0; i < 4; i++) d[i2][j][i] = 0.0f;
        gemm2_A1f<4, 4>((const uint2*)(smu + OFF_XH), mrow2, g_ffc1, 4,
                        kh * 16 + nh4 * 4, d, g, t);
        // epilogue: gelu + fragment-interleaved H store (uint2 per row-pair)
        uint2* H2w = (uint2*)(smu + OFF_Q);
#pragma unroll
        for (int jj = 0; jj < 2; jj++) {
            int j0 = 2 * jj;
            int j1 = 2 * jj + 1;
            int c0 = nh4 * 32 + 8 * j0 + 2 * t;
            int c1 = nh4 * 32 + 8 * j1 + 2 * t;
            float b00 = s_fc1b[kh * 128 + c0];
            float b01 = s_fc1b[kh * 128 + c0 + 1];
            float b10 = s_fc1b[kh * 128 + c1];
            float b11 = s_fc1b[kh * 128 + c1 + 1];
            int ks = kh * 8 + nh4 * 2 + jj;
#pragma unroll
            for (int i2 = 0; i2 < 2; i2++) {
                int r = mrow2 + i2 * 16 + g;
                float w00 = gelu1(d[i2][j0][0] + b00);
                float w01 = gelu1(d[i2][j0][1] + b01);
                float w02 = gelu1(d[i2][j0][2] + b00);
                float w03 = gelu1(d[i2][j0][3] + b01);
                float w10 = gelu1(d[i2][j1][0] + b10);
                float w11 = gelu1(d[i2][j1][1] + b11);
                float w12 = gelu1(d[i2][j1][2] + b10);
                float w13 = gelu1(d[i2][j1][3] + b11);
                int base = r * 68 + ks * 4 + t;     // uint2 index (stride 136 u32)
                H2w[base]          = make_uint2(packh1(w00, w01), packh1(w10, w11));
                H2w[base + 8 * 68] = make_uint2(packh1(w02, w03), packh1(w12, w13));
            }
        }
    }
    __syncthreads();

    float dacc[4][4];
#pragma unroll
    for (int j = 0; j < 4; j++)
#pragma unroll
        for (int i = 0; i < 4; i++) dacc[j][i] = 0.0f;
    gemm1_A1f<4, 16>((const uint2*)(smu + OFF_Q), mrow1, g_ffc2, 16, nh1 * 4, dacc, g, t);

    // h2 -> V region (Vt dead; H untouched by these stores)
#pragma unroll
    for (int j = 0; j < 4; j++) {
        int c = nh1 * 32 + 8 * j + 2 * t;
        float b0 = s_fc2b[c];
        float b1 = s_fc2b[c + 1];
        *(float2*)(sm + OFF_V + (mrow1 + g) * LD + c)     = make_float2(dacc[j][0] + b0, dacc[j][1] + b1);
        *(float2*)(sm + OFF_V + (mrow1 + g + 8) * LD + c) = make_float2(dacc[j][2] + b0, dacc[j][3] + b1);
    }
    __syncthreads();

    // ---- phase 5: LN2 fused with final residual + store ----
    {
        int row = tid >> 2;
        int pp = tid & 3;
        const float* h2 = sm + OFF_V + row * LD + pp * 16;
        float s = 0.0f;
#pragma unroll
        for (int c = 0; c < 16; c++) s += h2[c];
        s += __shfl_xor_sync(0xffffffffu, s, 1);
        s += __shfl_xor_sync(0xffffffffu, s, 2);
        float mean = s * (1.0f / 64.0f);
        float vv = 0.0f;
#pragma unroll
        for (int c = 0; c < 16; c++) {
            float d2 = h2[c] - mean;
            vv += d2 * d2;
        }
        vv += __shfl_xor_sync(0xffffffffu, vv, 1);
        vv += __shfl_xor_sync(0xffffffffu, vv, 2);
        float rstd = rsqrtf(vv * (1.0f / 64.0f) + 1e-5f);

        int gbase = token_gaddr(blockIdx.x, row);
#pragma unroll
        for (int q = 0; q < 4; q++) {
            int c = pp * 16 + q * 4;
            float4 xv = *(const float4*)(sm + OFF_X + row * LD + c);
            float4 hv = *(const float4*)(sm + OFF_V + row * LD + c);
            float4 ov;
            ov.x = xv.x + (hv.x - mean) * rstd * s_n2g[c]     + s_n2b[c];
            ov.y = xv.y + (hv.y - mean) * rstd * s_n2g[c + 1] + s_n2b[c + 1];
            ov.z = xv.z + (hv.z - mean) * rstd * s_n2g[c + 2] + s_n2b[c + 2];
            ov.w = xv.w + (hv.w - mean) * rstd * s_n2g[c + 3] + s_n2b[c + 3];
            *(float4*)(out + gbase + c) = ov;
        }
    }
}

// ---------------------------------------------------------------------------
extern "C" void kernel_launch(void* const* d_in, const int* in_sizes, int n_in,
                              void* d_out, int out_size) {
    const float* x      = (const float*)d_in[0];
    const float* qkv_w  = (const float*)d_in[1];
    const float* qkv_b  = (const float*)d_in[2];
    const float* proj_w = (const float*)d_in[3];
    const float* proj_b = (const float*)d_in[4];
    const float* lscale = (const float*)d_in[5];
    const float* cpb_w1 = (const float*)d_in[6];
    const float* cpb_b1 = (const float*)d_in[7];
    const float* cpb_w2 = (const float*)d_in[8];
    const float* n1g    = (const float*)d_in[9];
    const float* n1b    = (const float*)d_in[10];
    const float* n2g    = (const float*)d_in[11];
    const float* n2b    = (const float*)d_in[12];
    const float* fc1_w  = (const float*)d_in[13];
    const float* fc1_b  = (const float*)d_in[14];
    const float* fc2_w  = (const float*)d_in[15];
    const float* fc2_b  = (const float*)d_in[16];
    float* out = (float*)d_out;

    cudaFuncSetAttribute(swin_kernel, cudaFuncAttributeMaxDynamicSharedMemorySize, SMEM_BYTES);

    cpb_kernel<<<196, 128>>>(cpb_w1, cpb_b1, cpb_w2);
    expand_kernel<<<4, 256>>>(lscale);
    wsplit_kernel<<<48, 256>>>(qkv_w, proj_w, fc1_w, fc2_w);
    swin_kernel<<<8192, NTHREADS, SMEM_BYTES>>>(x, qkv_b, proj_b,
                                                n1g, n1b, n2g, n2b,
                                                fc1_b, fc2_b, out);
}

// round 16
// speedup vs baseline: 1.0395x; 1.0395x over previous
#include <cuda_runtime.h>
#include <cuda_fp16.h>
#include <cstdint>
#include <math.h>

// SwinTransformerBlockV2 fused kernel, v13 = v11 + merged-MLP barriers.
// Shift (8,8) multiple of window (4,4) => shift cancels, mask == 0.
// Tensor-core everything, FP16 fragments.
// Precision: qkv GEMM + attention S = 3-MMA hi/lo (protects exp path).
// P single fp16, V single fp16, O single fp16 -> proj 1 MMA/octet.
// fc1/fc2: A single, B single (1 MMA).
// v13: fc1 both halves back-to-back (disjoint H columns), one barrier, then
// fc2 as a single KS=16 pass; h2 stores need no barrier (disjoint region).

#define NTHREADS 256
#define LD   68
#define LDHM 132     // u32 row stride for merged H (128 pairs + pad)

#define OFF_X    0          // f32 [64][68] x -> x1 in place
#define OFF_Q    4352       // f32 q; then bufA (proj partial, even warps); then H
#define OFF_K    8704       // f32 k; then bufB (odd warps); H spans Q+K
#define OFF_V    13056      // half Vt[ch][token] stride 136; then h2 (f32)
#define OFF_XH   17408      // u32 [64][36] x split hi -> x1 packed fp16
#define OFF_XL   19712      // u32 [64][36] x split lo (dead after qkv)
#define OFF_HH   OFF_Q      // u32 [64][132] fc1+gelu packed fp16 (8448 <= 8704)
#define SMEM_FLOATS 22016
#define SMEM_BYTES  (SMEM_FLOATS * 4)

__device__ float g_tab[49 * 4];
__device__ float g_biasf[4 * 256];   // fragment layout: [hh][lane][8]
__device__ float g_scale[4];

// fragment-ready weights:
// qkv: uint4 {hi0,hi1,lo0,lo1} (3-term); others: uint2 {hi0,hi1} (single fp16)
__device__ uint4 g_fqkv[3072];
__device__ uint2 g_fproj[1024];
__device__ uint2 g_ffc1[4096];
__device__ uint2 g_ffc2[4096];

// ---------------------------------------------------------------------------
// fp16 pack/split helpers
// ---------------------------------------------------------------------------
__device__ __forceinline__ uint32_t packh1(float x, float y) {
    __half2 h = __floats2half2_rn(x, y);   // x in low half
    return *reinterpret_cast<uint32_t*>(&h);
}

__device__ __forceinline__ uint32_t splith(float x, float y, uint32_t& lo) {
    __half2 h = __floats2half2_rn(x, y);
    float2 f = __half22float2(h);
    __half2 l = __floats2half2_rn(x - f.x, y - f.y);
    lo = *reinterpret_cast<uint32_t*>(&l);
    return *reinterpret_cast<uint32_t*>(&h);
}

// ---------------------------------------------------------------------------
// Setup kernels
// ---------------------------------------------------------------------------
__device__ __forceinline__ float cpb_coord(int d) {
    float t = (8.0f / 3.0f) * (float)d;
    float v = log2f(fabsf(t) + 1.0f) / 3.0f;
    return (t < 0.0f) ? -v : v;
}

__global__ void cpb_kernel(const float* __restrict__ w1, const float* __restrict__ b1,
                           const float* __restrict__ w2) {
    int q = blockIdx.x >> 2;
    int h = blockIdx.x & 3;
    int a = q / 7;
    int b = q % 7;
    float c0 = cpb_coord(a - 3);
    float c1 = cpb_coord(b - 3);
    int tid = threadIdx.x;
    float s = 0.0f;
#pragma unroll
    for (int r = 0; r < 4; r++) {
        int j = tid + r * 128;
        float u = c0 * w1[2 * j] + c1 * w1[2 * j + 1] + b1[j];
        u = fmaxf(u, 0.0f);
        s += u * w2[h * 512 + j];
    }
    __shared__ float red[4];
#pragma unroll
    for (int o = 16; o > 0; o >>= 1) s += __shfl_xor_sync(0xffffffffu, s, o);
    if ((tid & 31) == 0) red[tid >> 5] = s;
    __syncthreads();
    if (tid == 0) g_tab[q * 4 + h] = red[0] + red[1] + red[2] + red[3];
}

__global__ void expand_kernel(const float* __restrict__ ls) {
    int e = blockIdx.x * 256 + threadIdx.x;   // 0..1023
    int hh = e >> 8;
    int lane = (e >> 3) & 31;
    int i = e & 7;
    int g = lane >> 2;
    int t = lane & 3;
    int r = g + ((i & 2) ? 8 : 0);
    int c = 2 * t + (i & 1) + ((i & 4) ? 8 : 0);
    int idx = ((r >> 2) - (c >> 2) + 3) * 7 + ((r & 3) - (c & 3) + 3);
    float v = g_tab[idx * 4 + hh];
    g_biasf[hh * 256 + lane * 8 + i] = 16.0f / (1.0f + expf(-v));
    if (e < 4) g_scale[e] = expf(fminf(ls[e], logf(100.0f)));
}

__global__ void wsplit_kernel(const float* __restrict__ qkv_w, const float* __restrict__ proj_w,
                              const float* __restrict__ fc1_w, const float* __restrict__ fc2_w) {
    int i = blockIdx.x * 256 + threadIdx.x;
    if (i >= 12288) return;
    const float* src;
    int q, K, lgKS, mode;
    uint4* dst4 = 0;
    uint2* dst2 = 0;
    if (i < 3072) {
        q = i; src = qkv_w; dst4 = g_fqkv; K = 64; lgKS = 2; mode = 0;
    } else if (i < 4096) {
        q = i - 3072; src = proj_w; dst2 = g_fproj; K = 64; lgKS = 2; mode = 1;
    } else if (i < 8192) {
        q = i - 4096; src = fc1_w; dst2 = g_ffc1; K = 64; lgKS = 2; mode = 1;
    } else {
        q = i - 8192; src = fc2_w; dst2 = g_ffc2; K = 256; lgKS = 4; mode = 1;
    }
    int t  = q & 3;
    int g  = (q >> 2) & 7;
    int ks = (q >> 5) & ((1 << lgKS) - 1);
    int o  = q >> (5 + lgKS);
    int n  = o * 8 + g;
    int p0 = ks * 8 + t;
    int p1 = p0 + 4;
    const float* row = src + n * K;
    if (mode == 0) {
        uint32_t lo0, lo1;
        uint32_t hi0 = splith(row[2 * p0], row[2 * p0 + 1], lo0);
        uint32_t hi1 = splith(row[2 * p1], row[2 * p1 + 1], lo1);
        dst4[q] = make_uint4(hi0, hi1, lo0, lo1);
    } else {
        uint32_t hi0 = packh1(row[2 * p0], row[2 * p0 + 1]);
        uint32_t hi1 = packh1(row[2 * p1], row[2 * p1 + 1]);
        dst2[q] = make_uint2(hi0, hi1);
    }
}

// ---------------------------------------------------------------------------
// mma helpers (fp16)
// ---------------------------------------------------------------------------
__device__ __forceinline__ void mma_f16(float* dd,
        uint32_t a0, uint32_t a1, uint32_t a2, uint32_t a3,
        uint32_t b0, uint32_t b1) {
    asm volatile("mma.sync.aligned.m16n8k16.row.col.f32.f16.f16.f32 "
                 "{%0,%1,%2,%3}, {%4,%5,%6,%7}, {%8,%9}, {%0,%1,%2,%3};\n"
                 : "+f"(dd[0]), "+f"(dd[1]), "+f"(dd[2]), "+f"(dd[3])
                 : "r"(a0), "r"(a1), "r"(a2), "r"(a3), "r"(b0), "r"(b1));
}

// M2 3-term (qkv): A pre-split (stride 36), B uint4 prefetched
template<int NT, int KSTEPS>
__device__ __forceinline__ void gemm2_A3(const uint32_t* Ah, const uint32_t* Al,
        int mrow, const uint4* __restrict__ Bf, int KS_total, int ks0, int o0,
        float (&d)[2][NT][4], int g, int t) {
    uint4 bn[NT];
#pragma unroll
    for (int j = 0; j < NT; j++)
        bn[j] = Bf[(o0 + j) * (KS_total * 32) + ks0 * 32 + g * 4 + t];
#pragma unroll
    for (int ks = 0; ks < KSTEPS; ks++) {
        uint4 bc[NT];
#pragma unroll
        for (int j = 0; j < NT; j++) bc[j] = bn[j];
        if (ks + 1 < KSTEPS) {
#pragma unroll
            for (int j = 0; j < NT; j++)
                bn[j] = Bf[(o0 + j) * (KS_total * 32) + (ks0 + ks + 1) * 32 + g * 4 + t];
        }
        uint32_t ah[2][4], al[2][4];
#pragma unroll
        for (int i2 = 0; i2 < 2; i2++) {
            int ar = (mrow + i2 * 16 + g) * 36 + ks * 8 + t;
            ah[i2][0] = Ah[ar];
            ah[i2][1] = Ah[ar + 8 * 36];
            ah[i2][2] = Ah[ar + 4];
            ah[i2][3] = Ah[ar + 8 * 36 + 4];
            al[i2][0] = Al[ar];
            al[i2][1] = Al[ar + 8 * 36];
            al[i2][2] = Al[ar + 4];
            al[i2][3] = Al[ar + 8 * 36 + 4];
        }
#pragma unroll
        for (int j = 0; j < NT; j++) {
#pragma unroll
            for (int i2 = 0; i2 < 2; i2++) {
                mma_f16(d[i2][j], ah[i2][0], ah[i2][1], ah[i2][2], ah[i2][3], bc[j].x, bc[j].y);
                mma_f16(d[i2][j], al[i2][0], al[i2][1], al[i2][2], al[i2][3], bc[j].x, bc[j].y);
                mma_f16(d[i2][j], ah[i2][0], ah[i2][1], ah[i2][2], ah[i2][3], bc[j].z, bc[j].w);
            }
        }
    }
}

// M2 single-term (fc1): A packed fp16 (stride 36), B uint2 prefetched, 1 MMA/step
template<int NT, int KSTEPS>
__device__ __forceinline__ void gemm2_A1(const uint32_t* Ah,
        int mrow, const uint2* __restrict__ Bf, int KS_total, int ks0, int o0,
        float (&d)[2][NT][4], int g, int t) {
    uint2 bn[NT];
#pragma unroll
    for (int j = 0; j < NT; j++)
        bn[j] = Bf[(o0 + j) * (KS_total * 32) + ks0 * 32 + g * 4 + t];
#pragma unroll
    for (int ks = 0; ks < KSTEPS; ks++) {
        uint2 bc[NT];
#pragma unroll
        for (int j = 0; j < NT; j++) bc[j] = bn[j];
        if (ks + 1 < KSTEPS) {
#pragma unroll
            for (int j = 0; j < NT; j++)
                bn[j] = Bf[(o0 + j) * (KS_total * 32) + (ks0 + ks + 1) * 32 + g * 4 + t];
        }
        uint32_t ah[2][4];
#pragma unroll
        for (int i2 = 0; i2 < 2; i2++) {
            int ar = (mrow + i2 * 16 + g) * 36 + ks * 8 + t;
            ah[i2][0] = Ah[ar];
            ah[i2][1] = Ah[ar + 8 * 36];
            ah[i2][2] = Ah[ar + 4];
            ah[i2][3] = Ah[ar + 8 * 36 + 4];
        }
#pragma unroll
        for (int j = 0; j < NT; j++) {
#pragma unroll
            for (int i2 = 0; i2 < 2; i2++) {
                mma_f16(d[i2][j], ah[i2][0], ah[i2][1], ah[i2][2], ah[i2][3], bc[j].x, bc[j].y);
            }
        }
    }
}

// M1 single-term (fc2): A packed fp16 (stride lda2), B uint2 prefetched, 1 MMA/step
template<int NT, int KSTEPS>
__device__ __forceinline__ void gemm1_A1(const uint32_t* Ah,
        int lda2, int mrow,
        const uint2* __restrict__ Bf, int KS_total, int ks0, int o0,
        float (&d)[NT][4], int g, int t) {
    uint2 bn[NT];
#pragma unroll
    for (int j = 0; j < NT; j++)
        bn[j] = Bf[(o0 + j) * (KS_total * 32) + ks0 * 32 + g * 4 + t];
#pragma unroll
    for (int ks = 0; ks < KSTEPS; ks++) {
        uint2 bc[NT];
#pragma unroll
        for (int j = 0; j < NT; j++) bc[j] = bn[j];
        if (ks + 1 < KSTEPS) {
#pragma unroll
            for (int j = 0; j < NT; j++)
                bn[j] = Bf[(o0 + j) * (KS_total * 32) + (ks0 + ks + 1) * 32 + g * 4 + t];
        }
        int ar = (mrow + g) * lda2 + ks * 8 + t;
        uint32_t ah0 = Ah[ar];
        uint32_t ah1 = Ah[ar + 8 * lda2];
        uint32_t ah2 = Ah[ar + 4];
        uint32_t ah3 = Ah[ar + 8 * lda2 + 4];
#pragma unroll
        for (int j = 0; j < NT; j++) {
            mma_f16(d[j], ah0, ah1, ah2, ah3, bc[j].x, bc[j].y);
        }
    }
}

__device__ __forceinline__ int token_gaddr(int blk, int lt) {
    int wi = blk * 4 + (lt >> 4);
    int n  = lt & 15;
    int b  = wi >> 12;
    int r  = wi & 4095;
    int wh = r >> 6;
    int ww = r & 63;
    int row = wh * 4 + (n >> 2);
    int col = ww * 4 + (n & 3);
    return ((b * 256 + row) * 256 + col) * 64;
}

// ---------------------------------------------------------------------------
__global__ __launch_bounds__(NTHREADS, 2)
void swin_kernel(const float* __restrict__ x,
                 const float* __restrict__ qkv_b, const float* __restrict__ proj_b,
                 const float* __restrict__ n1g, const float* __restrict__ n1b,
                 const float* __restrict__ n2g, const float* __restrict__ n2b,
                 const float* __restrict__ fc1_b, const float* __restrict__ fc2_b,
                 float* __restrict__ out) {
    extern __shared__ float sm[];
    uint32_t* smu = (uint32_t*)sm;
    __shared__ float s_qkvb[192];
    __shared__ float s_projb[64];
    __shared__ float s_fc1b[256];
    __shared__ float s_fc2b[64];
    __shared__ float s_n1g[64];
    __shared__ float s_n1b[64];
    __shared__ float s_n2g[64];
    __shared__ float s_n2b[64];
    __shared__ float s_scale[4];

    const int tid  = threadIdx.x;
    const int warp = tid >> 5;
    const int lane = tid & 31;
    const int g = lane >> 2;
    const int t = lane & 3;
    const int mt2 = warp >> 2;
    const int nh4 = warp & 3;
    const int mrow2 = mt2 * 32;
    const int mt1 = warp & 3;
    const int nh1 = warp >> 2;
    const int mrow1 = mt1 * 16;

    // ---- phase 0: params + x tile (f32 + split) ----
    if (tid < 192) s_qkvb[tid] = (tid >= 64 && tid < 128) ? 0.0f : qkv_b[tid];
    if (tid < 64) {
        s_projb[tid] = proj_b[tid];
        s_fc2b[tid]  = fc2_b[tid];
        s_n1g[tid] = n1g[tid];
        s_n1b[tid] = n1b[tid];
        s_n2g[tid] = n2g[tid];
        s_n2b[tid] = n2b[tid];
    }
    s_fc1b[tid] = fc1_b[tid];
    if (tid >= 192 && tid < 196) s_scale[tid - 192] = g_scale[tid - 192];

    {
        int lt = tid >> 2;
        int pp = tid & 3;
        int gbase = token_gaddr(blockIdx.x, lt);
        const float4* xp = (const float4*)(x + gbase + pp * 16);
        float4* xd = (float4*)(sm + OFF_X + lt * LD + pp * 16);
        uint32_t* xh = smu + OFF_XH + lt * 36 + pp * 8;
        uint32_t* xl = smu + OFF_XL + lt * 36 + pp * 8;
#pragma unroll
        for (int i = 0; i < 4; i++) {
            float4 v4 = xp[i];
            xd[i] = v4;
            uint32_t lo0, lo1;
            uint32_t hi0 = splith(v4.x, v4.y, lo0);
            uint32_t hi1 = splith(v4.z, v4.w, lo1);
            xh[2 * i] = hi0;
            xh[2 * i + 1] = hi1;
            xl[2 * i] = lo0;
            xl[2 * i + 1] = lo1;
        }
    }
    __syncthreads();

    // ---- phase 1: QKV GEMM (M2, 3-term, NT=6); V -> half Vt ----
    __half* vt = (__half*)(sm + OFF_V);
    {
        float d[2][6][4];
#pragma unroll
        for (int i2 = 0; i2 < 2; i2++)
#pragma unroll
            for (int j = 0; j < 6; j++)
#pragma unroll
                for (int i = 0; i < 4; i++) d[i2][j][i] = 0.0f;
        gemm2_A3<6, 4>(smu + OFF_XH, smu + OFF_XL, mrow2, g_fqkv, 4, 0, nh4 * 6, d, g, t);
#pragma unroll
        for (int j = 0; j < 6; j++) {
            int c = nh4 * 48 + 8 * j + 2 * t;
            float b0 = s_qkvb[c];
            float b1 = s_qkvb[c + 1];
            if (c < 128) {
                int col = c & 63;
                float* dst = sm + (c < 64 ? OFF_Q : OFF_K);
#pragma unroll
                for (int i2 = 0; i2 < 2; i2++) {
                    int r = mrow2 + i2 * 16 + g;
                    *(float2*)(dst + r * LD + col)       = make_float2(d[i2][j][0] + b0, d[i2][j][1] + b1);
                    *(float2*)(dst + (r + 8) * LD + col) = make_float2(d[i2][j][2] + b0, d[i2][j][3] + b1);
                }
            } else {
                int col = c - 128;   // V channel -> transposed HALF store Vt[ch][token]
#pragma unroll
                for (int i2 = 0; i2 < 2; i2++) {
                    int r = mrow2 + i2 * 16 + g;
                    vt[col * 136 + r]           = __float2half_rn(d[i2][j][0] + b0);
                    vt[(col + 1) * 136 + r]     = __float2half_rn(d[i2][j][1] + b1);
                    vt[col * 136 + r + 8]       = __float2half_rn(d[i2][j][2] + b0);
                    vt[(col + 1) * 136 + r + 8] = __float2half_rn(d[i2][j][3] + b1);
                }
            }
        }
    }
    __syncthreads();

    // ---- phase 2: attention (S 3-term; P,V,O single fp16) + chained proj ----
    {
        float cacc[8][4];
        bool wbias = ((warp & 1) == 0);
#pragma unroll
        for (int j = 0; j < 8; j++) {
            float b0 = wbias ? s_projb[8 * j + 2 * t] : 0.0f;
            float b1 = wbias ? s_projb[8 * j + 2 * t + 1] : 0.0f;
            cacc[j][0] = b0;
            cacc[j][1] = b1;
            cacc[j][2] = b0;
            cacc[j][3] = b1;
        }
        int wl = warp >> 1;
        int r0 = wl * 16;
        const uint32_t* vtu = (const uint32_t*)(sm + OFF_V);

#pragma unroll 1
        for (int it = 0; it < 2; it++) {
            int hh = (warp & 1) * 2 + it;

            const float* Qb = sm + OFF_Q + (r0 + g) * LD + hh * 16;
            float2 q0 = *(const float2*)(Qb + 2 * t);
            float2 q1 = *(const float2*)(Qb + 2 * t + 8);
            float2 q2 = *(const float2*)(Qb + 8 * LD + 2 * t);
            float2 q3 = *(const float2*)(Qb + 8 * LD + 2 * t + 8);
            float ssA = q0.x * q0.x + q0.y * q0.y + q1.x * q1.x + q1.y * q1.y;
            float ssB = q2.x * q2.x + q2.y * q2.y + q3.x * q3.x + q3.y * q3.y;
            ssA += __shfl_xor_sync(0xffffffffu, ssA, 1);
            ssA += __shfl_xor_sync(0xffffffffu, ssA, 2);
            ssB += __shfl_xor_sync(0xffffffffu, ssB, 1);
            ssB += __shfl_xor_sync(0xffffffffu, ssB, 2);
            float scl = s_scale[hh];
            float iA = scl * rsqrtf(fmaxf(ssA, 1e-24f));
            float iB = scl * rsqrtf(fmaxf(ssB, 1e-24f));
            q0.x *= iA; q0.y *= iA; q1.x *= iA; q1.y *= iA;
            q2.x *= iB; q2.y *= iB; q3.x *= iB; q3.y *= iB;

            const float* Kb = sm + OFF_K + (r0 + g) * LD + hh * 16;
            float2 k0 = *(const float2*)(Kb + 2 * t);
            float2 k1 = *(const float2*)(Kb + 2 * t + 8);
            float2 k2 = *(const float2*)(Kb + 8 * LD + 2 * t);
            float2 k3 = *(const float2*)(Kb + 8 * LD + 2 * t + 8);
            float skA = k0.x * k0.x + k0.y * k0.y + k1.x * k1.x + k1.y * k1.y;
            float skB = k2.x * k2.x + k2.y * k2.y + k3.x * k3.x + k3.y * k3.y;
            skA += __shfl_xor_sync(0xffffffffu, skA, 1);
            skA += __shfl_xor_sync(0xffffffffu, skA, 2);
            skB += __shfl_xor_sync(0xffffffffu, skB, 1);
            skB += __shfl_xor_sync(0xffffffffu, skB, 2);
            float jA = rsqrtf(fmaxf(skA, 1e-24f));
            float jB = rsqrtf(fmaxf(skB, 1e-24f));
            k0.x *= jA; k0.y *= jA; k1.x *= jA; k1.y *= jA;
            k2.x *= jB; k2.y *= jB; k3.x *= jB; k3.y *= jB;

            uint32_t ql0, ql1, ql2, ql3, kl0, kl1, kl2, kl3;
            uint32_t qh0 = splith(q0.x, q0.y, ql0);
            uint32_t qh1 = splith(q1.x, q1.y, ql1);
            uint32_t qh2 = splith(q2.x, q2.y, ql2);
            uint32_t qh3 = splith(q3.x, q3.y, ql3);
            uint32_t kh0 = splith(k0.x, k0.y, kl0);
            uint32_t kh1 = splith(k1.x, k1.y, kl1);
            uint32_t kh2 = splith(k2.x, k2.y, kl2);
            uint32_t kh3 = splith(k3.x, k3.y, kl3);

            const float4* bf = (const float4*)(g_biasf + hh * 256 + lane * 8);
            float4 bb0 = bf[0];
            float4 bb1 = bf[1];
            float s0[4] = {bb0.x, bb0.y, bb0.z, bb0.w};
            float s1[4] = {bb1.x, bb1.y, bb1.z, bb1.w};
            mma_f16(s0, qh0, qh2, qh1, qh3, kh0, kh1);
            mma_f16(s0, ql0, ql2, ql1, ql3, kh0, kh1);
            mma_f16(s0, qh0, qh2, qh1, qh3, kl0, kl1);
            mma_f16(s1, qh0, qh2, qh1, qh3, kh2, kh3);
            mma_f16(s1, ql0, ql2, ql1, ql3, kh2, kh3);
            mma_f16(s1, qh0, qh2, qh1, qh3, kl2, kl3);

            float mA = fmaxf(fmaxf(s0[0], s0[1]), fmaxf(s1[0], s1[1]));
            float mB = fmaxf(fmaxf(s0[2], s0[3]), fmaxf(s1[2], s1[3]));
            mA = fmaxf(mA, __shfl_xor_sync(0xffffffffu, mA, 1));
            mA = fmaxf(mA, __shfl_xor_sync(0xffffffffu, mA, 2));
            mB = fmaxf(mB, __shfl_xor_sync(0xffffffffu, mB, 1));
            mB = fmaxf(mB, __shfl_xor_sync(0xffffffffu, mB, 2));
            s0[0] = __expf(s0[0] - mA);
            s0[1] = __expf(s0[1] - mA);
            s1[0] = __expf(s1[0] - mA);
            s1[1] = __expf(s1[1] - mA);
            s0[2] = __expf(s0[2] - mB);
            s0[3] = __expf(s0[3] - mB);
            s1[2] = __expf(s1[2] - mB);
            s1[3] = __expf(s1[3] - mB);
            float suA = s0[0] + s0[1] + s1[0] + s1[1];
            float suB = s0[2] + s0[3] + s1[2] + s1[3];
            suA += __shfl_xor_sync(0xffffffffu, suA, 1);
            suA += __shfl_xor_sync(0xffffffffu, suA, 2);
            suB += __shfl_xor_sync(0xffffffffu, suB, 1);
            suB += __shfl_xor_sync(0xffffffffu, suB, 2);
            float ivA = 1.0f / suA;
            float ivB = 1.0f / suB;

            // P single fp16 fragments
            uint32_t ph0 = packh1(s0[0], s0[1]);
            uint32_t ph1 = packh1(s0[2], s0[3]);
            uint32_t ph2 = packh1(s1[0], s1[1]);
            uint32_t ph3 = packh1(s1[2], s1[3]);

            // V b-frags: direct u32 loads of packed half2 from Vt
            int ch = hh * 16 + g;
            int vbase = ch * 68 + (r0 >> 1) + t;
            uint32_t vh0 = vtu[vbase];
            uint32_t vh1 = vtu[vbase + 4];
            uint32_t vh2 = vtu[vbase + 8 * 68];
            uint32_t vh3 = vtu[vbase + 8 * 68 + 4];

            float o0[4] = {0.0f, 0.0f, 0.0f, 0.0f};
            float o1[4] = {0.0f, 0.0f, 0.0f, 0.0f};
            mma_f16(o0, ph0, ph1, ph2, ph3, vh0, vh1);
            mma_f16(o1, ph0, ph1, ph2, ph3, vh2, vh3);

            o0[0] *= ivA; o0[1] *= ivA; o1[0] *= ivA; o1[1] *= ivA;
            o0[2] *= ivB; o0[3] *= ivB; o1[2] *= ivB; o1[3] *= ivB;

            // chain: O single fp16 -> proj 1 MMA per octet
            uint32_t ahx0 = packh1(o0[0], o0[1]);
            uint32_t ahx1 = packh1(o0[2], o0[3]);
            uint32_t ahx2 = packh1(o1[0], o1[1]);
            uint32_t ahx3 = packh1(o1[2], o1[3]);
#pragma unroll
            for (int j = 0; j < 8; j++) {
                uint2 b = g_fproj[j * 128 + hh * 32 + g * 4 + t];
                mma_f16(cacc[j], ahx0, ahx1, ahx2, ahx3, b.x, b.y);
            }
        }
        // all Q/K/V reads done before overwriting Q/K with partials
        __syncthreads();
        float* buf = sm + ((warp & 1) ? OFF_K : OFF_Q);
#pragma unroll
        for (int j = 0; j < 8; j++) {
            int c = 8 * j + 2 * t;
            *(float2*)(buf + (r0 + g) * LD + c)     = make_float2(cacc[j][0], cacc[j][1]);
            *(float2*)(buf + (r0 + g + 8) * LD + c) = make_float2(cacc[j][2], cacc[j][3]);
        }
    }
    __syncthreads();

    // ---- phase 3: LN1 ('a' = bufA+bufB) + residual in place + pack x1 fp16 ----
    {
        int row = tid >> 2;
        int sub = tid & 3;
        const float* pa = sm + OFF_Q + row * LD + sub * 16;
        const float* pb = sm + OFF_K + row * LD + sub * 16;
        float av[16];
        float s = 0.0f;
#pragma unroll
        for (int c = 0; c < 16; c++) {
            av[c] = pa[c] + pb[c];
            s += av[c];
        }
        s += __shfl_xor_sync(0xffffffffu, s, 1);
        s += __shfl_xor_sync(0xffffffffu, s, 2);
        float mean = s * (1.0f / 64.0f);
        float vv = 0.0f;
#pragma unroll
        for (int c = 0; c < 16; c++) {
            float d2 = av[c] - mean;
            vv += d2 * d2;
        }
        vv += __shfl_xor_sync(0xffffffffu, vv, 1);
        vv += __shfl_xor_sync(0xffffffffu, vv, 2);
        float rstd = rsqrtf(vv * (1.0f / 64.0f) + 1e-5f);
        float* xr = sm + OFF_X + row * LD + sub * 16;
        const float* gg = s_n1g + sub * 16;
        const float* bbv = s_n1b + sub * 16;
        uint32_t* xh = smu + OFF_XH + row * 36 + sub * 8;
#pragma unroll
        for (int c2 = 0; c2 < 8; c2++) {
            float u0 = xr[2 * c2]     + (av[2 * c2]     - mean) * rstd * gg[2 * c2]     + bbv[2 * c2];
            float u1 = xr[2 * c2 + 1] + (av[2 * c2 + 1] - mean) * rstd * gg[2 * c2 + 1] + bbv[2 * c2 + 1];
            xr[2 * c2] = u0;
            xr[2 * c2 + 1] = u1;
            xh[c2] = packh1(u0, u1);
        }
    }
    __syncthreads();

    // ---- phase 4: MLP — fc1 both halves, one barrier, fc2 single KS=16 ----
#pragma unroll 1
    for (int kh = 0; kh < 2; kh++) {
        float d[2][4][4];
#pragma unroll
        for (int i2 = 0; i2 < 2; i2++)
#pragma unroll
            for (int j = 0; j < 4; j++)
#pragma unroll
                for (int i = 0; i < 4; i++) d[i2][j][i] = 0.0f;
        gemm2_A1<4, 4>(smu + OFF_XH, mrow2, g_ffc1, 4, 0,
                       kh * 16 + nh4 * 4, d, g, t);
#pragma unroll
        for (int j = 0; j < 4; j++) {
            int c = nh4 * 32 + 8 * j + 2 * t;
            float b0 = s_fc1b[kh * 128 + c];
            float b1 = s_fc1b[kh * 128 + c + 1];
            int col2 = kh * 64 + nh4 * 16 + 4 * j + t;   // pair index 0..127
#pragma unroll
            for (int i2 = 0; i2 < 2; i2++) {
                float v0 = d[i2][j][0] + b0;
                float v1 = d[i2][j][1] + b1;
                float v2 = d[i2][j][2] + b0;
                float v3 = d[i2][j][3] + b1;
                v0 = v0 * 0.5f * (1.0f + erff(v0 * 0.70710678118654752f));
                v1 = v1 * 0.5f * (1.0f + erff(v1 * 0.70710678118654752f));
                v2 = v2 * 0.5f * (1.0f + erff(v2 * 0.70710678118654752f));
                v3 = v3 * 0.5f * (1.0f + erff(v3 * 0.70710678118654752f));
                int r = mrow2 + i2 * 16 + g;
                smu[OFF_HH + r * LDHM + col2]       = packh1(v0, v1);
                smu[OFF_HH + (r + 8) * LDHM + col2] = packh1(v2, v3);
            }
        }
    }
    __syncthreads();

    float dacc[4][4];
#pragma unroll
    for (int j = 0; j < 4; j++)
#pragma unroll
        for (int i = 0; i < 4; i++) dacc[j][i] = 0.0f;
    gemm1_A1<4, 16>(smu + OFF_HH, LDHM, mrow1, g_ffc2, 16, 0, nh1 * 4, dacc, g, t);

    // h2 -> V region (disjoint from H; no barrier needed before these stores)
#pragma unroll
    for (int j = 0; j < 4; j++) {
        int c = nh1 * 32 + 8 * j + 2 * t;
        float b0 = s_fc2b[c];
        float b1 = s_fc2b[c + 1];
        *(float2*)(sm + OFF_V + (mrow1 + g) * LD + c)     = make_float2(dacc[j][0] + b0, dacc[j][1] + b1);
        *(float2*)(sm + OFF_V + (mrow1 + g + 8) * LD + c) = make_float2(dacc[j][2] + b0, dacc[j][3] + b1);
    }
    __syncthreads();

    // ---- phase 5: LN2 fused with final residual + store ----
    {
        int row = tid >> 2;
        int pp = tid & 3;
        const float* h2 = sm + OFF_V + row * LD + pp * 16;
        float s = 0.0f;
#pragma unroll
        for (int c = 0; c < 16; c++) s += h2[c];
        s += __shfl_xor_sync(0xffffffffu, s, 1);
        s += __shfl_xor_sync(0xffffffffu, s, 2);
        float mean = s * (1.0f / 64.0f);
        float vv = 0.0f;
#pragma unroll
        for (int c = 0; c < 16; c++) {
            float d2 = h2[c] - mean;
            vv += d2 * d2;
        }
        vv += __shfl_xor_sync(0xffffffffu, vv, 1);
        vv += __shfl_xor_sync(0xffffffffu, vv, 2);
        float rstd = rsqrtf(vv * (1.0f / 64.0f) + 1e-5f);

        int gbase = token_gaddr(blockIdx.x, row);
#pragma unroll
        for (int q = 0; q < 4; q++) {
            int c = pp * 16 + q * 4;
            float4 xv = *(const float4*)(sm + OFF_X + row * LD + c);
            float4 hv = *(const float4*)(sm + OFF_V + row * LD + c);
            float4 ov;
            ov.x = xv.x + (hv.x - mean) * rstd * s_n2g[c]     + s_n2b[c];
            ov.y = xv.y + (hv.y - mean) * rstd * s_n2g[c + 1] + s_n2b[c + 1];
            ov.z = xv.z + (hv.z - mean) * rstd * s_n2g[c + 2] + s_n2b[c + 2];
            ov.w = xv.w + (hv.w - mean) * rstd * s_n2g[c + 3] + s_n2b[c + 3];
            *(float4*)(out + gbase + c) = ov;
        }
    }
}

// ---------------------------------------------------------------------------
extern "C" void kernel_launch(void* const* d_in, const int* in_sizes, int n_in,
                              void* d_out, int out_size) {
    const float* x      = (const float*)d_in[0];
    const float* qkv_w  = (const float*)d_in[1];
    const float* qkv_b  = (const float*)d_in[2];
    const float* proj_w = (const float*)d_in[3];
    const float* proj_b = (const float*)d_in[4];
    const float* lscale = (const float*)d_in[5];
    const float* cpb_w1 = (const float*)d_in[6];
    const float* cpb_b1 = (const float*)d_in[7];
    const float* cpb_w2 = (const float*)d_in[8];
    const float* n1g    = (const float*)d_in[9];
    const float* n1b    = (const float*)d_in[10];
    const float* n2g    = (const float*)d_in[11];
    const float* n2b    = (const float*)d_in[12];
    const float* fc1_w  = (const float*)d_in[13];
    const float* fc1_b  = (const float*)d_in[14];
    const float* fc2_w  = (const float*)d_in[15];
    const float* fc2_b  = (const float*)d_in[16];
    float* out = (float*)d_out;

    cudaFuncSetAttribute(swin_kernel, cudaFuncAttributeMaxDynamicSharedMemorySize, SMEM_BYTES);

    cpb_kernel<<<196, 128>>>(cpb_w1, cpb_b1, cpb_w2);
    expand_kernel<<<4, 256>>>(lscale);
    wsplit_kernel<<<48, 256>>>(qkv_w, proj_w, fc1_w, fc2_w);
    swin_kernel<<<8192, NTHREADS, SMEM_BYTES>>>(x, qkv_b, proj_b,
                                                n1g, n1b, n2g, n2b,
                                                fc1_b, fc2_b, out);
}

// round 17
// speedup vs baseline: 1.0413x; 1.0017x over previous
#include <cuda_runtime.h>
#include <cuda_fp16.h>
#include <cstdint>
#include <math.h>

// SwinTransformerBlockV2 fused kernel, v14 = v13 + independent 128-thread
// groups (2 windows each) with named barriers -> 4 independent streams/SM.
// Shift (8,8) multiple of window (4,4) => shift cancels, mask == 0.
// Precision: qkv + attention S = 3-MMA fp16 hi/lo; P/V/O single fp16;
// proj/fc1/fc2 B single fp16; fc1/fc2 A single fp16.

#define NTHREADS 256
#define LD   68
#define LDHM 132     // u32 row stride for H chunks
#define HCH  2176    // u32 size of one group quarter of Q/K region

#define OFF_X    0          // f32 [64][68] x -> x1 in place
#define OFF_Q    4352       // f32 q; then bufA; then H chunk0 (per group)
#define OFF_K    8704       // f32 k; then bufB; then H chunk1 (per group)
#define OFF_V    13056      // half Vt[ch][token] stride 136
#define OFF_XH   17408      // u32 [64][36] x split hi -> x1 packed fp16
#define OFF_XL   19712      // u32 [64][36] x split lo (dead after qkv)
#define OFF_H2   22016      // f32 [64][68] h2 (dedicated)
#define SMEM_FLOATS 26368
#define SMEM_BYTES  (SMEM_FLOATS * 4)

__device__ float g_tab[49 * 4];
__device__ float g_biasf[4 * 256];   // fragment layout: [hh][lane][8]
__device__ float g_scale[4];

__device__ uint4 g_fqkv[3072];
__device__ uint2 g_fproj[1024];
__device__ uint2 g_ffc1[4096];
__device__ uint2 g_ffc2[4096];

// ---------------------------------------------------------------------------
__device__ __forceinline__ void gbar(int id) {
    asm volatile("bar.sync %0, %1;" :: "r"(id), "r"(128) : "memory");
}

__device__ __forceinline__ uint32_t packh1(float x, float y) {
    __half2 h = __floats2half2_rn(x, y);
    return *reinterpret_cast<uint32_t*>(&h);
}

__device__ __forceinline__ uint32_t splith(float x, float y, uint32_t& lo) {
    __half2 h = __floats2half2_rn(x, y);
    float2 f = __half22float2(h);
    __half2 l = __floats2half2_rn(x - f.x, y - f.y);
    lo = *reinterpret_cast<uint32_t*>(&l);
    return *reinterpret_cast<uint32_t*>(&h);
}

// ---------------------------------------------------------------------------
// Setup kernels
// ---------------------------------------------------------------------------
__device__ __forceinline__ float cpb_coord(int d) {
    float t = (8.0f / 3.0f) * (float)d;
    float v = log2f(fabsf(t) + 1.0f) / 3.0f;
    return (t < 0.0f) ? -v : v;
}

__global__ void cpb_kernel(const float* __restrict__ w1, const float* __restrict__ b1,
                           const float* __restrict__ w2) {
    int q = blockIdx.x >> 2;
    int h = blockIdx.x & 3;
    int a = q / 7;
    int b = q % 7;
    float c0 = cpb_coord(a - 3);
    float c1 = cpb_coord(b - 3);
    int tid = threadIdx.x;
    float s = 0.0f;
#pragma unroll
    for (int r = 0; r < 4; r++) {
        int j = tid + r * 128;
        float u = c0 * w1[2 * j] + c1 * w1[2 * j + 1] + b1[j];
        u = fmaxf(u, 0.0f);
        s += u * w2[h * 512 + j];
    }
    __shared__ float red[4];
#pragma unroll
    for (int o = 16; o > 0; o >>= 1) s += __shfl_xor_sync(0xffffffffu, s, o);
    if ((tid & 31) == 0) red[tid >> 5] = s;
    __syncthreads();
    if (tid == 0) g_tab[q * 4 + h] = red[0] + red[1] + red[2] + red[3];
}

__global__ void expand_kernel(const float* __restrict__ ls) {
    int e = blockIdx.x * 256 + threadIdx.x;
    int hh = e >> 8;
    int lane = (e >> 3) & 31;
    int i = e & 7;
    int g = lane >> 2;
    int t = lane & 3;
    int r = g + ((i & 2) ? 8 : 0);
    int c = 2 * t + (i & 1) + ((i & 4) ? 8 : 0);
    int idx = ((r >> 2) - (c >> 2) + 3) * 7 + ((r & 3) - (c & 3) + 3);
    float v = g_tab[idx * 4 + hh];
    g_biasf[hh * 256 + lane * 8 + i] = 16.0f / (1.0f + expf(-v));
    if (e < 4) g_scale[e] = expf(fminf(ls[e], logf(100.0f)));
}

__global__ void wsplit_kernel(const float* __restrict__ qkv_w, const float* __restrict__ proj_w,
                              const float* __restrict__ fc1_w, const float* __restrict__ fc2_w) {
    int i = blockIdx.x * 256 + threadIdx.x;
    if (i >= 12288) return;
    const float* src;
    int q, K, lgKS, mode;
    uint4* dst4 = 0;
    uint2* dst2 = 0;
    if (i < 3072) {
        q = i; src = qkv_w; dst4 = g_fqkv; K = 64; lgKS = 2; mode = 0;
    } else if (i < 4096) {
        q = i - 3072; src = proj_w; dst2 = g_fproj; K = 64; lgKS = 2; mode = 1;
    } else if (i < 8192) {
        q = i - 4096; src = fc1_w; dst2 = g_ffc1; K = 64; lgKS = 2; mode = 1;
    } else {
        q = i - 8192; src = fc2_w; dst2 = g_ffc2; K = 256; lgKS = 4; mode = 1;
    }
    int t  = q & 3;
    int g  = (q >> 2) & 7;
    int ks = (q >> 5) & ((1 << lgKS) - 1);
    int o  = q >> (5 + lgKS);
    int n  = o * 8 + g;
    int p0 = ks * 8 + t;
    int p1 = p0 + 4;
    const float* row = src + n * K;
    if (mode == 0) {
        uint32_t lo0, lo1;
        uint32_t hi0 = splith(row[2 * p0], row[2 * p0 + 1], lo0);
        uint32_t hi1 = splith(row[2 * p1], row[2 * p1 + 1], lo1);
        dst4[q] = make_uint4(hi0, hi1, lo0, lo1);
    } else {
        uint32_t hi0 = packh1(row[2 * p0], row[2 * p0 + 1]);
        uint32_t hi1 = packh1(row[2 * p1], row[2 * p1 + 1]);
        dst2[q] = make_uint2(hi0, hi1);
    }
}

// ---------------------------------------------------------------------------
__device__ __forceinline__ void mma_f16(float* dd,
        uint32_t a0, uint32_t a1, uint32_t a2, uint32_t a3,
        uint32_t b0, uint32_t b1) {
    asm volatile("mma.sync.aligned.m16n8k16.row.col.f32.f16.f16.f32 "
                 "{%0,%1,%2,%3}, {%4,%5,%6,%7}, {%8,%9}, {%0,%1,%2,%3};\n"
                 : "+f"(dd[0]), "+f"(dd[1]), "+f"(dd[2]), "+f"(dd[3])
                 : "r"(a0), "r"(a1), "r"(a2), "r"(a3), "r"(b0), "r"(b1));
}

// M2 3-term (qkv): A pre-split (stride 36), B uint4 prefetched
template<int NT, int KSTEPS>
__device__ __forceinline__ void gemm2_A3(const uint32_t* Ah, const uint32_t* Al,
        int mrow, const uint4* __restrict__ Bf, int KS_total, int ks0, int o0,
        float (&d)[2][NT][4], int g, int t) {
    uint4 bn[NT];
#pragma unroll
    for (int j = 0; j < NT; j++)
        bn[j] = Bf[(o0 + j) * (KS_total * 32) + ks0 * 32 + g * 4 + t];
#pragma unroll
    for (int ks = 0; ks < KSTEPS; ks++) {
        uint4 bc[NT];
#pragma unroll
        for (int j = 0; j < NT; j++) bc[j] = bn[j];
        if (ks + 1 < KSTEPS) {
#pragma unroll
            for (int j = 0; j < NT; j++)
                bn[j] = Bf[(o0 + j) * (KS_total * 32) + (ks0 + ks + 1) * 32 + g * 4 + t];
        }
        uint32_t ah[2][4], al[2][4];
#pragma unroll
        for (int i2 = 0; i2 < 2; i2++) {
            int ar = (mrow + i2 * 16 + g) * 36 + ks * 8 + t;
            ah[i2][0] = Ah[ar];
            ah[i2][1] = Ah[ar + 8 * 36];
            ah[i2][2] = Ah[ar + 4];
            ah[i2][3] = Ah[ar + 8 * 36 + 4];
            al[i2][0] = Al[ar];
            al[i2][1] = Al[ar + 8 * 36];
            al[i2][2] = Al[ar + 4];
            al[i2][3] = Al[ar + 8 * 36 + 4];
        }
#pragma unroll
        for (int j = 0; j < NT; j++) {
#pragma unroll
            for (int i2 = 0; i2 < 2; i2++) {
                mma_f16(d[i2][j], ah[i2][0], ah[i2][1], ah[i2][2], ah[i2][3], bc[j].x, bc[j].y);
                mma_f16(d[i2][j], al[i2][0], al[i2][1], al[i2][2], al[i2][3], bc[j].x, bc[j].y);
                mma_f16(d[i2][j], ah[i2][0], ah[i2][1], ah[i2][2], ah[i2][3], bc[j].z, bc[j].w);
            }
        }
    }
}

// M2 single-term (fc1): A packed fp16 (stride 36), B uint2 prefetched
template<int NT, int KSTEPS>
__device__ __forceinline__ void gemm2_A1(const uint32_t* Ah,
        int mrow, const uint2* __restrict__ Bf, int KS_total, int ks0, int o0,
        float (&d)[2][NT][4], int g, int t) {
    uint2 bn[NT];
#pragma unroll
    for (int j = 0; j < NT; j++)
        bn[j] = Bf[(o0 + j) * (KS_total * 32) + ks0 * 32 + g * 4 + t];
#pragma unroll
    for (int ks = 0; ks < KSTEPS; ks++) {
        uint2 bc[NT];
#pragma unroll
        for (int j = 0; j < NT; j++) bc[j] = bn[j];
        if (ks + 1 < KSTEPS) {
#pragma unroll
            for (int j = 0; j < NT; j++)
                bn[j] = Bf[(o0 + j) * (KS_total * 32) + (ks0 + ks + 1) * 32 + g * 4 + t];
        }
        uint32_t ah[2][4];
#pragma unroll
        for (int i2 = 0; i2 < 2; i2++) {
            int ar = (mrow + i2 * 16 + g) * 36 + ks * 8 + t;
            ah[i2][0] = Ah[ar];
            ah[i2][1] = Ah[ar + 8 * 36];
            ah[i2][2] = Ah[ar + 4];
            ah[i2][3] = Ah[ar + 8 * 36 + 4];
        }
#pragma unroll
        for (int j = 0; j < NT; j++) {
#pragma unroll
            for (int i2 = 0; i2 < 2; i2++) {
                mma_f16(d[i2][j], ah[i2][0], ah[i2][1], ah[i2][2], ah[i2][3], bc[j].x, bc[j].y);
            }
        }
    }
}

// M1 single-term (fc2): A packed fp16 (stride lda2), rows g/g+8 of given base
template<int NT, int KSTEPS>
__device__ __forceinline__ void gemm1_A1(const uint32_t* Ah,
        int lda2, int mrow,
        const uint2* __restrict__ Bf, int KS_total, int ks0, int o0,
        float (&d)[NT][4], int g, int t) {
    uint2 bn[NT];
#pragma unroll
    for (int j = 0; j < NT; j++)
        bn[j] = Bf[(o0 + j) * (KS_total * 32) + ks0 * 32 + g * 4 + t];
#pragma unroll
    for (int ks = 0; ks < KSTEPS; ks++) {
        uint2 bc[NT];
#pragma unroll
        for (int j = 0; j < NT; j++) bc[j] = bn[j];
        if (ks + 1 < KSTEPS) {
#pragma unroll
            for (int j = 0; j < NT; j++)
                bn[j] = Bf[(o0 + j) * (KS_total * 32) + (ks0 + ks + 1) * 32 + g * 4 + t];
        }
        int ar = (mrow + g) * lda2 + ks * 8 + t;
        uint32_t ah0 = Ah[ar];
        uint32_t ah1 = Ah[ar + 8 * lda2];
        uint32_t ah2 = Ah[ar + 4];
        uint32_t ah3 = Ah[ar + 8 * lda2 + 4];
#pragma unroll
        for (int j = 0; j < NT; j++) {
            mma_f16(d[j], ah0, ah1, ah2, ah3, bc[j].x, bc[j].y);
        }
    }
}

__device__ __forceinline__ int token_gaddr(int blk, int lt) {
    int wi = blk * 4 + (lt >> 4);
    int n  = lt & 15;
    int b  = wi >> 12;
    int r  = wi & 4095;
    int wh = r >> 6;
    int ww = r & 63;
    int row = wh * 4 + (n >> 2);
    int col = ww * 4 + (n & 3);
    return ((b * 256 + row) * 256 + col) * 64;
}

// ---------------------------------------------------------------------------
__global__ __launch_bounds__(NTHREADS, 2)
void swin_kernel(const float* __restrict__ x,
                 const float* __restrict__ qkv_b, const float* __restrict__ proj_b,
                 const float* __restrict__ n1g, const float* __restrict__ n1b,
                 const float* __restrict__ n2g, const float* __restrict__ n2b,
                 const float* __restrict__ fc1_b, const float* __restrict__ fc2_b,
                 float* __restrict__ out) {
    extern __shared__ float sm[];
    uint32_t* smu = (uint32_t*)sm;
    __shared__ float s_qkvb[192];
    __shared__ float s_projb[64];
    __shared__ float s_fc1b[256];
    __shared__ float s_fc2b[64];
    __shared__ float s_n1g[64];
    __shared__ float s_n1b[64];
    __shared__ float s_n2g[64];
    __shared__ float s_n2b[64];
    __shared__ float s_scale[4];

    const int tid  = threadIdx.x;
    const int warp = tid >> 5;
    const int lane = tid & 31;
    const int g = lane >> 2;
    const int t = lane & 3;
    const int grp = warp >> 2;       // 0 or 1 (independent 128-thread group)
    const int wg  = warp & 3;        // warp in group
    const int bid = grp + 1;         // named barrier id
    const int R0  = grp * 32;        // group token-row base
    const int mrow2 = R0;            // M2 base (i2 covers +0/+16)
    const int nh4 = wg;              // n-quarter for QKV/fc1

    // ---- phase 0: params + x tile (f32 + split); ends with FULL sync ----
    if (tid < 192) s_qkvb[tid] = (tid >= 64 && tid < 128) ? 0.0f : qkv_b[tid];
    if (tid < 64) {
        s_projb[tid] = proj_b[tid];
        s_fc2b[tid]  = fc2_b[tid];
        s_n1g[tid] = n1g[tid];
        s_n1b[tid] = n1b[tid];
        s_n2g[tid] = n2g[tid];
        s_n2b[tid] = n2b[tid];
    }
    s_fc1b[tid] = fc1_b[tid];
    if (tid >= 192 && tid < 196) s_scale[tid - 192] = g_scale[tid - 192];

    {
        int lt = tid >> 2;
        int pp = tid & 3;
        int gbase = token_gaddr(blockIdx.x, lt);
        const float4* xp = (const float4*)(x + gbase + pp * 16);
        float4* xd = (float4*)(sm + OFF_X + lt * LD + pp * 16);
        uint32_t* xh = smu + OFF_XH + lt * 36 + pp * 8;
        uint32_t* xl = smu + OFF_XL + lt * 36 + pp * 8;
#pragma unroll
        for (int i = 0; i < 4; i++) {
            float4 v4 = xp[i];
            xd[i] = v4;
            uint32_t lo0, lo1;
            uint32_t hi0 = splith(v4.x, v4.y, lo0);
            uint32_t hi1 = splith(v4.z, v4.w, lo1);
            xh[2 * i] = hi0;
            xh[2 * i + 1] = hi1;
            xl[2 * i] = lo0;
            xl[2 * i + 1] = lo1;
        }
    }
    __syncthreads();

    // ---- phase 1: QKV GEMM (M2, 3-term, NT=6); V -> half Vt ----
    __half* vt = (__half*)(sm + OFF_V);
    {
        float d[2][6][4];
#pragma unroll
        for (int i2 = 0; i2 < 2; i2++)
#pragma unroll
            for (int j = 0; j < 6; j++)
#pragma unroll
                for (int i = 0; i < 4; i++) d[i2][j][i] = 0.0f;
        gemm2_A3<6, 4>(smu + OFF_XH, smu + OFF_XL, mrow2, g_fqkv, 4, 0, nh4 * 6, d, g, t);
#pragma unroll
        for (int j = 0; j < 6; j++) {
            int c = nh4 * 48 + 8 * j + 2 * t;
            float b0 = s_qkvb[c];
            float b1 = s_qkvb[c + 1];
            if (c < 128) {
                int col = c & 63;
                float* dst = sm + (c < 64 ? OFF_Q : OFF_K);
#pragma unroll
                for (int i2 = 0; i2 < 2; i2++) {
                    int r = mrow2 + i2 * 16 + g;
                    *(float2*)(dst + r * LD + col)       = make_float2(d[i2][j][0] + b0, d[i2][j][1] + b1);
                    *(float2*)(dst + (r + 8) * LD + col) = make_float2(d[i2][j][2] + b0, d[i2][j][3] + b1);
                }
            } else {
                int col = c - 128;   // V channel -> transposed HALF store Vt[ch][token]
#pragma unroll
                for (int i2 = 0; i2 < 2; i2++) {
                    int r = mrow2 + i2 * 16 + g;
                    vt[col * 136 + r]           = __float2half_rn(d[i2][j][0] + b0);
                    vt[(col + 1) * 136 + r]     = __float2half_rn(d[i2][j][1] + b1);
                    vt[col * 136 + r + 8]       = __float2half_rn(d[i2][j][2] + b0);
                    vt[(col + 1) * 136 + r + 8] = __float2half_rn(d[i2][j][3] + b1);
                }
            }
        }
    }
    gbar(bid);

    // ---- phase 2: attention (S 3-term; P,V,O single fp16) + chained proj ----
    {
        float cacc[8][4];
        bool wbias = ((wg & 1) == 0);
#pragma unroll
        for (int j = 0; j < 8; j++) {
            float b0 = wbias ? s_projb[8 * j + 2 * t] : 0.0f;
            float b1 = wbias ? s_projb[8 * j + 2 * t + 1] : 0.0f;
            cacc[j][0] = b0;
            cacc[j][1] = b1;
            cacc[j][2] = b0;
            cacc[j][3] = b1;
        }
        int r0 = R0 + (wg >> 1) * 16;
        const uint32_t* vtu = (const uint32_t*)(sm + OFF_V);

#pragma unroll 1
        for (int it = 0; it < 2; it++) {
            int hh = (wg & 1) * 2 + it;

            const float* Qb = sm + OFF_Q + (r0 + g) * LD + hh * 16;
            float2 q0 = *(const float2*)(Qb + 2 * t);
            float2 q1 = *(const float2*)(Qb + 2 * t + 8);
            float2 q2 = *(const float2*)(Qb + 8 * LD + 2 * t);
            float2 q3 = *(const float2*)(Qb + 8 * LD + 2 * t + 8);
            float ssA = q0.x * q0.x + q0.y * q0.y + q1.x * q1.x + q1.y * q1.y;
            float ssB = q2.x * q2.x + q2.y * q2.y + q3.x * q3.x + q3.y * q3.y;
            ssA += __shfl_xor_sync(0xffffffffu, ssA, 1);
            ssA += __shfl_xor_sync(0xffffffffu, ssA, 2);
            ssB += __shfl_xor_sync(0xffffffffu, ssB, 1);
            ssB += __shfl_xor_sync(0xffffffffu, ssB, 2);
            float scl = s_scale[hh];
            float iA = scl * rsqrtf(fmaxf(ssA, 1e-24f));
            float iB = scl * rsqrtf(fmaxf(ssB, 1e-24f));
            q0.x *= iA; q0.y *= iA; q1.x *= iA; q1.y *= iA;
            q2.x *= iB; q2.y *= iB; q3.x *= iB; q3.y *= iB;

            const float* Kb = sm + OFF_K + (r0 + g) * LD + hh * 16;
            float2 k0 = *(const float2*)(Kb + 2 * t);
            float2 k1 = *(const float2*)(Kb + 2 * t + 8);
            float2 k2 = *(const float2*)(Kb + 8 * LD + 2 * t);
            float2 k3 = *(const float2*)(Kb + 8 * LD + 2 * t + 8);
            float skA = k0.x * k0.x + k0.y * k0.y + k1.x * k1.x + k1.y * k1.y;
            float skB = k2.x * k2.x + k2.y * k2.y + k3.x * k3.x + k3.y * k3.y;
            skA += __shfl_xor_sync(0xffffffffu, skA, 1);
            skA += __shfl_xor_sync(0xffffffffu, skA, 2);
            skB += __shfl_xor_sync(0xffffffffu, skB, 1);
            skB += __shfl_xor_sync(0xffffffffu, skB, 2);
            float jA = rsqrtf(fmaxf(skA, 1e-24f));
            float jB = rsqrtf(fmaxf(skB, 1e-24f));
            k0.x *= jA; k0.y *= jA; k1.x *= jA; k1.y *= jA;
            k2.x *= jB; k2.y *= jB; k3.x *= jB; k3.y *= jB;

            uint32_t ql0, ql1, ql2, ql3, kl0, kl1, kl2, kl3;
            uint32_t qh0 = splith(q0.x, q0.y, ql0);
            uint32_t qh1 = splith(q1.x, q1.y, ql1);
            uint32_t qh2 = splith(q2.x, q2.y, ql2);
            uint32_t qh3 = splith(q3.x, q3.y, ql3);
            uint32_t kh0 = splith(k0.x, k0.y, kl0);
            uint32_t kh1 = splith(k1.x, k1.y, kl1);
            uint32_t kh2 = splith(k2.x, k2.y, kl2);
            uint32_t kh3 = splith(k3.x, k3.y, kl3);

            const float4* bf = (const float4*)(g_biasf + hh * 256 + lane * 8);
            float4 bb0 = bf[0];
            float4 bb1 = bf[1];
            float s0[4] = {bb0.x, bb0.y, bb0.z, bb0.w};
            float s1[4] = {bb1.x, bb1.y, bb1.z, bb1.w};
            mma_f16(s0, qh0, qh2, qh1, qh3, kh0, kh1);
            mma_f16(s0, ql0, ql2, ql1, ql3, kh0, kh1);
            mma_f16(s0, qh0, qh2, qh1, qh3, kl0, kl1);
            mma_f16(s1, qh0, qh2, qh1, qh3, kh2, kh3);
            mma_f16(s1, ql0, ql2, ql1, ql3, kh2, kh3);
            mma_f16(s1, qh0, qh2, qh1, qh3, kl2, kl3);

            float mA = fmaxf(fmaxf(s0[0], s0[1]), fmaxf(s1[0], s1[1]));
            float mB = fmaxf(fmaxf(s0[2], s0[3]), fmaxf(s1[2], s1[3]));
            mA = fmaxf(mA, __shfl_xor_sync(0xffffffffu, mA, 1));
            mA = fmaxf(mA, __shfl_xor_sync(0xffffffffu, mA, 2));
            mB = fmaxf(mB, __shfl_xor_sync(0xffffffffu, mB, 1));
            mB = fmaxf(mB, __shfl_xor_sync(0xffffffffu, mB, 2));
            s0[0] = __expf(s0[0] - mA);
            s0[1] = __expf(s0[1] - mA);
            s1[0] = __expf(s1[0] - mA);
            s1[1] = __expf(s1[1] - mA);
            s0[2] = __expf(s0[2] - mB);
            s0[3] = __expf(s0[3] - mB);
            s1[2] = __expf(s1[2] - mB);
            s1[3] = __expf(s1[3] - mB);
            float suA = s0[0] + s0[1] + s1[0] + s1[1];
            float suB = s0[2] + s0[3] + s1[2] + s1[3];
            suA += __shfl_xor_sync(0xffffffffu, suA, 1);
            suA += __shfl_xor_sync(0xffffffffu, suA, 2);
            suB += __shfl_xor_sync(0xffffffffu, suB, 1);
            suB += __shfl_xor_sync(0xffffffffu, suB, 2);
            float ivA = 1.0f / suA;
            float ivB = 1.0f / suB;

            uint32_t ph0 = packh1(s0[0], s0[1]);
            uint32_t ph1 = packh1(s0[2], s0[3]);
            uint32_t ph2 = packh1(s1[0], s1[1]);
            uint32_t ph3 = packh1(s1[2], s1[3]);

            int ch = hh * 16 + g;
            int vbase = ch * 68 + (r0 >> 1) + t;
            uint32_t vh0 = vtu[vbase];
            uint32_t vh1 = vtu[vbase + 4];
            uint32_t vh2 = vtu[vbase + 8 * 68];
            uint32_t vh3 = vtu[vbase + 8 * 68 + 4];

            float o0[4] = {0.0f, 0.0f, 0.0f, 0.0f};
            float o1[4] = {0.0f, 0.0f, 0.0f, 0.0f};
            mma_f16(o0, ph0, ph1, ph2, ph3, vh0, vh1);
            mma_f16(o1, ph0, ph1, ph2, ph3, vh2, vh3);

            o0[0] *= ivA; o0[1] *= ivA; o1[0] *= ivA; o1[1] *= ivA;
            o0[2] *= ivB; o0[3] *= ivB; o1[2] *= ivB; o1[3] *= ivB;

            uint32_t ahx0 = packh1(o0[0], o0[1]);
            uint32_t ahx1 = packh1(o0[2], o0[3]);
            uint32_t ahx2 = packh1(o1[0], o1[1]);
            uint32_t ahx3 = packh1(o1[2], o1[3]);
#pragma unroll
            for (int j = 0; j < 8; j++) {
                uint2 b = g_fproj[j * 128 + hh * 32 + g * 4 + t];
                mma_f16(cacc[j], ahx0, ahx1, ahx2, ahx3, b.x, b.y);
            }
        }
        // group's Q/K/Vt reads done before overwriting its Q/K rows
        gbar(bid);
        float* buf = sm + ((wg & 1) ? OFF_K : OFF_Q);
#pragma unroll
        for (int j = 0; j < 8; j++) {
            int c = 8 * j + 2 * t;
            *(float2*)(buf + (r0 + g) * LD + c)     = make_float2(cacc[j][0], cacc[j][1]);
            *(float2*)(buf + (r0 + g + 8) * LD + c) = make_float2(cacc[j][2], cacc[j][3]);
        }
    }
    gbar(bid);

    // ---- phase 3: LN1 ('a' = bufA+bufB) + residual in place + pack x1 fp16 ----
    {
        int row = tid >> 2;       // group0 threads -> rows 0..31, group1 -> 32..63
        int sub = tid & 3;
        const float* pa = sm + OFF_Q + row * LD + sub * 16;
        const float* pb = sm + OFF_K + row * LD + sub * 16;
        float av[16];
        float s = 0.0f;
#pragma unroll
        for (int c = 0; c < 16; c++) {
            av[c] = pa[c] + pb[c];
            s += av[c];
        }
        s += __shfl_xor_sync(0xffffffffu, s, 1);
        s += __shfl_xor_sync(0xffffffffu, s, 2);
        float mean = s * (1.0f / 64.0f);
        float vv = 0.0f;
#pragma unroll
        for (int c = 0; c < 16; c++) {
            float d2 = av[c] - mean;
            vv += d2 * d2;
        }
        vv += __shfl_xor_sync(0xffffffffu, vv, 1);
        vv += __shfl_xor_sync(0xffffffffu, vv, 2);
        float rstd = rsqrtf(vv * (1.0f / 64.0f) + 1e-5f);
        float* xr = sm + OFF_X + row * LD + sub * 16;
        const float* gg = s_n1g + sub * 16;
        const float* bbv = s_n1b + sub * 16;
        uint32_t* xh = smu + OFF_XH + row * 36 + sub * 8;
#pragma unroll
        for (int c2 = 0; c2 < 8; c2++) {
            float u0 = xr[2 * c2]     + (av[2 * c2]     - mean) * rstd * gg[2 * c2]     + bbv[2 * c2];
            float u1 = xr[2 * c2 + 1] + (av[2 * c2 + 1] - mean) * rstd * gg[2 * c2 + 1] + bbv[2 * c2 + 1];
            xr[2 * c2] = u0;
            xr[2 * c2 + 1] = u1;
            xh[c2] = packh1(u0, u1);
        }
    }
    gbar(bid);

    // ---- phase 4: MLP — fc1 both halves into chunked H, barrier, fc2 ----
    {
        int base0 = OFF_Q + grp * HCH;   // H chunk for local rows 0..15
        int base1 = OFF_K + grp * HCH;   // H chunk for local rows 16..31
#pragma unroll 1
        for (int kh = 0; kh < 2; kh++) {
            float d[2][4][4];
#pragma unroll
            for (int i2 = 0; i2 < 2; i2++)
#pragma unroll
                for (int j = 0; j < 4; j++)
#pragma unroll
                    for (int i = 0; i < 4; i++) d[i2][j][i] = 0.0f;
            gemm2_A1<4, 4>(smu + OFF_XH, mrow2, g_ffc1, 4, 0,
                           kh * 16 + nh4 * 4, d, g, t);
#pragma unroll
            for (int j = 0; j < 4; j++) {
                int c = nh4 * 32 + 8 * j + 2 * t;
                float b0 = s_fc1b[kh * 128 + c];
                float b1 = s_fc1b[kh * 128 + c + 1];
                int col2 = kh * 64 + nh4 * 16 + 4 * j + t;   // pair index 0..127
#pragma unroll
                for (int i2 = 0; i2 < 2; i2++) {
                    float v0 = d[i2][j][0] + b0;
                    float v1 = d[i2][j][1] + b1;
                    float v2 = d[i2][j][2] + b0;
                    float v3 = d[i2][j][3] + b1;
                    v0 = v0 * 0.5f * (1.0f + erff(v0 * 0.70710678118654752f));
                    v1 = v1 * 0.5f * (1.0f + erff(v1 * 0.70710678118654752f));
                    v2 = v2 * 0.5f * (1.0f + erff(v2 * 0.70710678118654752f));
                    v3 = v3 * 0.5f * (1.0f + erff(v3 * 0.70710678118654752f));
                    int cb = i2 ? base1 : base0;
                    smu[cb + g * LDHM + col2]       = packh1(v0, v1);
                    smu[cb + (g + 8) * LDHM + col2] = packh1(v2, v3);
                }
            }
        }
        gbar(bid);

        // fc2: 2m x 2n within group; tile = wg>>1 selects H chunk
        int tile = wg >> 1;
        int nh1 = wg & 1;
        int hbase = tile ? base1 : base0;
        float dacc[4][4];
#pragma unroll
        for (int j = 0; j < 4; j++)
#pragma unroll
            for (int i = 0; i < 4; i++) dacc[j][i] = 0.0f;
        gemm1_A1<4, 16>(smu + hbase, LDHM, 0, g_ffc2, 16, 0, nh1 * 4, dacc, g, t);

        // h2 -> dedicated region (no hazards)
        int orow = R0 + tile * 16;
#pragma unroll
        for (int j = 0; j < 4; j++) {
            int c = nh1 * 32 + 8 * j + 2 * t;
            float b0 = s_fc2b[c];
            float b1 = s_fc2b[c + 1];
            *(float2*)(sm + OFF_H2 + (orow + g) * LD + c)     = make_float2(dacc[j][0] + b0, dacc[j][1] + b1);
            *(float2*)(sm + OFF_H2 + (orow + g + 8) * LD + c) = make_float2(dacc[j][2] + b0, dacc[j][3] + b1);
        }
    }
    gbar(bid);

    // ---- phase 5: LN2 fused with final residual + store ----
    {
        int row = tid >> 2;
        int pp = tid & 3;
        const float* h2 = sm + OFF_H2 + row * LD + pp * 16;
        float s = 0.0f;
#pragma unroll
        for (int c = 0; c < 16; c++) s += h2[c];
        s += __shfl_xor_sync(0xffffffffu, s, 1);
        s += __shfl_xor_sync(0xffffffffu, s, 2);
        float mean = s * (1.0f / 64.0f);
        float vv = 0.0f;
#pragma unroll
        for (int c = 0; c < 16; c++) {
            float d2 = h2[c] - mean;
            vv += d2 * d2;
        }
        vv += __shfl_xor_sync(0xffffffffu, vv, 1);
        vv += __shfl_xor_sync(0xffffffffu, vv, 2);
        float rstd = rsqrtf(vv * (1.0f / 64.0f) + 1e-5f);

        int gbase = token_gaddr(blockIdx.x, row);
#pragma unroll
        for (int q = 0; q < 4; q++) {
            int c = pp * 16 + q * 4;
            float4 xv = *(const float4*)(sm + OFF_X + row * LD + c);
            float4 hv = *(const float4*)(sm + OFF_H2 + row * LD + c);
            float4 ov;
            ov.x = xv.x + (hv.x - mean) * rstd * s_n2g[c]     + s_n2b[c];
            ov.y = xv.y + (hv.y - mean) * rstd * s_n2g[c + 1] + s_n2b[c + 1];
            ov.z = xv.z + (hv.z - mean) * rstd * s_n2g[c + 2] + s_n2b[c + 2];
            ov.w = xv.w + (hv.w - mean) * rstd * s_n2g[c + 3] + s_n2b[c + 3];
            *(float4*)(out + gbase + c) = ov;
        }
    }
}

// ---------------------------------------------------------------------------
extern "C" void kernel_launch(void* const* d_in, const int* in_sizes, int n_in,
                              void* d_out, int out_size) {
    const float* x      = (const float*)d_in[0];
    const float* qkv_w  = (const float*)d_in[1];
    const float* qkv_b  = (const float*)d_in[2];
    const float* proj_w = (const float*)d_in[3];
    const float* proj_b = (const float*)d_in[4];
    const float* lscale = (const float*)d_in[5];
    const float* cpb_w1 = (const float*)d_in[6];
    const float* cpb_b1 = (const float*)d_in[7];
    const float* cpb_w2 = (const float*)d_in[8];
    const float* n1g    = (const float*)d_in[9];
    const float* n1b    = (const float*)d_in[10];
    const float* n2g    = (const float*)d_in[11];
    const float* n2b    = (const float*)d_in[12];
    const float* fc1_w  = (const float*)d_in[13];
    const float* fc1_b  = (const float*)d_in[14];
    const float* fc2_w  = (const float*)d_in[15];
    const float* fc2_b  = (const float*)d_in[16];
    float* out = (float*)d_out;

    cudaFuncSetAttribute(swin_kernel, cudaFuncAttributeMaxDynamicSharedMemorySize, SMEM_BYTES);

    cpb_kernel<<<196, 128>>>(cpb_w1, cpb_b1, cpb_w2);
    expand_kernel<<<4, 256>>>(lscale);
    wsplit_kernel<<<48, 256>>>(qkv_w, proj_w, fc1_w, fc2_w);
    swin_kernel<<<8192, NTHREADS, SMEM_BYTES>>>(x, qkv_b, proj_b,
                                                n1g, n1b, n2g, n2b,
                                                fc1_b, fc2_b, out);
}